// round 3
// baseline (speedup 1.0000x reference)
#include <cuda_runtime.h>
#include <cuda_fp16.h>
#include <cstdint>

#define N_NODES 100000
#define N_EDGES 1200000
#define D_NODE 64
#define HID 128
#define SW 136            // smem row stride in halfs (pad -> conflict-free mma frag loads)
#define TILE_M 128

// ---------------- device scratch (no allocs allowed) ----------------
__device__ int g_count[N_NODES];        // per-dest edge counts (zeroed by memset each iter)
__device__ int g_off[N_NODES + 1];      // CSR offsets
__device__ int g_cursor[N_NODES];       // fill cursors (init = offsets, by scan kernel)
__device__ int g_eid[N_EDGES];          // edge ids sorted by destination
// packed fp16 weight fragments (hi + lo split): [kt][ntile][lane] -> uint2 (b0,b1 of m16n8k16 B frag)
__device__ uint2 g_W0h[8 * 16 * 32], g_W0l[8 * 16 * 32];
__device__ uint2 g_W1h[8 * 16 * 32], g_W1l[8 * 16 * 32];
__device__ uint2 g_W2h[8 *  8 * 32], g_W2l[8 *  8 * 32];

// ---------------- helpers ----------------
__device__ __forceinline__ uint32_t f2_to_h2(float a, float b) {
    __half ha = __float2half_rn(a), hb = __float2half_rn(b);
    return (uint32_t)__half_as_ushort(ha) | ((uint32_t)__half_as_ushort(hb) << 16);
}
__device__ __forceinline__ float h_res(float a) {
    return a - __half2float(__float2half_rn(a));
}
__device__ __forceinline__ bool detect_i64(const int* ei) {
    // int64 layout => odd int32 words of first values (<100000, nonneg) are zero
    return (ei[1] == 0) & (ei[3] == 0) & (ei[5] == 0) & (ei[7] == 0);
}
__device__ __forceinline__ int dest_of(const int* ei, int e, bool is64) {
    if (is64) return (int)((const long long*)ei)[N_EDGES + e];
    return ei[N_EDGES + e];
}

__device__ __forceinline__ void mma16816(float c[4], const uint32_t a[4], uint2 b) {
    asm volatile(
        "mma.sync.aligned.m16n8k16.row.col.f32.f16.f16.f32 "
        "{%0,%1,%2,%3},{%4,%5,%6,%7},{%8,%9},{%0,%1,%2,%3};"
        : "+f"(c[0]), "+f"(c[1]), "+f"(c[2]), "+f"(c[3])
        : "r"(a[0]), "r"(a[1]), "r"(a[2]), "r"(a[3]), "r"(b.x), "r"(b.y));
}

// ---------------- weight pack: fp32 -> (hi, lo) fp16 mma B fragments ----------------
__global__ void pack_w_kernel(const float* __restrict__ W0,
                              const float* __restrict__ W1,
                              const float* __restrict__ W2) {
    int t = blockIdx.x * blockDim.x + threadIdx.x;
    if (t >= 10240) return;
    const float* W; uint2 *ph, *pl; int NT, Ncols, idx;
    if (t < 4096)       { W = W0; ph = g_W0h; pl = g_W0l; NT = 16; Ncols = 128; idx = t; }
    else if (t < 8192)  { W = W1; ph = g_W1h; pl = g_W1l; NT = 16; Ncols = 128; idx = t - 4096; }
    else                { W = W2; ph = g_W2h; pl = g_W2l; NT = 8;  Ncols = 64;  idx = t - 8192; }
    int lane = idx & 31, tile = idx >> 5;
    int nt = tile % NT, kt = tile / NT;
    int k0 = kt * 16 + (lane & 3) * 2;
    int n  = nt * 8  + (lane >> 2);
    float w00 = W[(k0    ) * Ncols + n];
    float w01 = W[(k0 + 1) * Ncols + n];
    float w10 = W[(k0 + 8) * Ncols + n];
    float w11 = W[(k0 + 9) * Ncols + n];
    ph[idx] = make_uint2(f2_to_h2(w00, w01), f2_to_h2(w10, w11));
    pl[idx] = make_uint2(f2_to_h2(h_res(w00), h_res(w01)), f2_to_h2(h_res(w10), h_res(w11)));
}

// ---------------- CSR build: histogram -> scan -> bucket scatter ----------------
__global__ void hist_kernel(const int* __restrict__ ei) {
    bool is64 = detect_i64(ei);
    int e = blockIdx.x * blockDim.x + threadIdx.x;
    if (e >= N_EDGES) return;
    atomicAdd(&g_count[dest_of(ei, e, is64)], 1);
}

__global__ __launch_bounds__(1024) void scan_kernel() {
    __shared__ int s_warp[32];
    const int t = threadIdx.x, lane = t & 31, wid = t >> 5;
    const int CH = (N_NODES + 1023) / 1024;  // 98
    int beg = t * CH;
    int end = min(beg + CH, N_NODES);
    int s = 0;
    for (int i = beg; i < end; i++) s += g_count[i];
    // inclusive warp scan of per-thread sums
    int x = s;
#pragma unroll
    for (int d = 1; d < 32; d <<= 1) {
        int y = __shfl_up_sync(0xffffffffu, x, d);
        if (lane >= d) x += y;
    }
    if (lane == 31) s_warp[wid] = x;
    __syncthreads();
    if (wid == 0) {
        int wv = s_warp[lane];
#pragma unroll
        for (int d = 1; d < 32; d <<= 1) {
            int y = __shfl_up_sync(0xffffffffu, wv, d);
            if (lane >= d) wv += y;
        }
        s_warp[lane] = wv - s_warp[lane];  // exclusive warp base
    }
    __syncthreads();
    int base = (x - s) + s_warp[wid];      // exclusive prefix for this thread
    int run = base;
    for (int i = beg; i < end; i++) {
        int c = g_count[i];
        g_off[i] = run;
        g_cursor[i] = run;
        run += c;
    }
    if (t == 1023) g_off[N_NODES] = run;   // last chunk empty -> run == total
}

__global__ void bucket_kernel(const int* __restrict__ ei) {
    bool is64 = detect_i64(ei);
    int e = blockIdx.x * blockDim.x + threadIdx.x;
    if (e >= N_EDGES) return;
    int d = dest_of(ei, e, is64);
    int pos = atomicAdd(&g_cursor[d], 1);
    g_eid[pos] = e;
}

// ---------------- fused gather + MLP + LayerNorm + residual ----------------
template <int NTW, int NTT>
__device__ __forceinline__ void gemm_layer(const __half* sh_hi, const __half* sh_lo,
                                           const uint2* __restrict__ Bh,
                                           const uint2* __restrict__ Bl,
                                           int warp_m, int ntile0, int lane,
                                           float acc[2][NTW][4]) {
#pragma unroll
    for (int mt = 0; mt < 2; mt++)
#pragma unroll
        for (int nt = 0; nt < NTW; nt++)
#pragma unroll
            for (int q = 0; q < 4; q++) acc[mt][nt][q] = 0.f;

    int rA  = warp_m + (lane >> 2);
    int cAq = (lane & 3) * 2;
#pragma unroll
    for (int kt = 0; kt < 8; kt++) {
        uint32_t Ah[2][4], Al[2][4];
        int cA = kt * 16 + cAq;
#pragma unroll
        for (int mt = 0; mt < 2; mt++) {
            int r = rA + mt * 16;
            Ah[mt][0] = *(const uint32_t*)(sh_hi + r * SW + cA);
            Ah[mt][1] = *(const uint32_t*)(sh_hi + (r + 8) * SW + cA);
            Ah[mt][2] = *(const uint32_t*)(sh_hi + r * SW + cA + 8);
            Ah[mt][3] = *(const uint32_t*)(sh_hi + (r + 8) * SW + cA + 8);
            Al[mt][0] = *(const uint32_t*)(sh_lo + r * SW + cA);
            Al[mt][1] = *(const uint32_t*)(sh_lo + (r + 8) * SW + cA);
            Al[mt][2] = *(const uint32_t*)(sh_lo + r * SW + cA + 8);
            Al[mt][3] = *(const uint32_t*)(sh_lo + (r + 8) * SW + cA + 8);
        }
#pragma unroll
        for (int nt = 0; nt < NTW; nt++) {
            int bi = (kt * NTT + ntile0 + nt) * 32 + lane;
            uint2 bh = __ldg(&Bh[bi]);
            uint2 bl = __ldg(&Bl[bi]);
#pragma unroll
            for (int mt = 0; mt < 2; mt++) {
                mma16816(acc[mt][nt], Ah[mt], bh);   // hi * hi
                mma16816(acc[mt][nt], Al[mt], bh);   // lo * hi
                mma16816(acc[mt][nt], Ah[mt], bl);   // hi * lo
            }
        }
    }
}

template <int NTW>
__device__ __forceinline__ void epilogue_relu(float acc[2][NTW][4],
                                              const float* __restrict__ bias,
                                              int warp_m, int ntile0, int lane,
                                              __half* sh_hi, __half* sh_lo) {
    __syncthreads();  // all warps done reading previous h
#pragma unroll
    for (int mt = 0; mt < 2; mt++)
#pragma unroll
        for (int nt = 0; nt < NTW; nt++) {
            int r0 = warp_m + mt * 16 + (lane >> 2);
            int c  = (ntile0 + nt) * 8 + (lane & 3) * 2;
            float bx = __ldg(&bias[c]), by = __ldg(&bias[c + 1]);
            float v0 = fmaxf(acc[mt][nt][0] + bx, 0.f);
            float v1 = fmaxf(acc[mt][nt][1] + by, 0.f);
            float v2 = fmaxf(acc[mt][nt][2] + bx, 0.f);
            float v3 = fmaxf(acc[mt][nt][3] + by, 0.f);
            *(uint32_t*)(sh_hi + r0 * SW + c)       = f2_to_h2(v0, v1);
            *(uint32_t*)(sh_lo + r0 * SW + c)       = f2_to_h2(h_res(v0), h_res(v1));
            *(uint32_t*)(sh_hi + (r0 + 8) * SW + c) = f2_to_h2(v2, v3);
            *(uint32_t*)(sh_lo + (r0 + 8) * SW + c) = f2_to_h2(h_res(v2), h_res(v3));
        }
    __syncthreads();
}

__global__ __launch_bounds__(256) void mlp_kernel(
    const float* __restrict__ x,
    const float* __restrict__ ea,
    const float* __restrict__ b0, const float* __restrict__ b1,
    const float* __restrict__ b2,
    const float* __restrict__ lng, const float* __restrict__ lnb,
    float* __restrict__ out) {
    extern __shared__ __align__(16) unsigned char smem_raw[];
    __half* sh_hi = (__half*)smem_raw;
    __half* sh_lo = sh_hi + 128 * SW;
    float*  s_stat = (float*)(sh_lo + 128 * SW);  // mu[128], rstd[128]

    int tid = threadIdx.x, lane = tid & 31, w = tid >> 5;
    int block0 = blockIdx.x * TILE_M;

    // ---- stage h0 = [x | gathered segment-sum] as fp16 hi/lo ----
    // warp w handles rows [w*16, w*16+16); lane covers a float2 column pair
    const float2* x2  = (const float2*)x;
    const float2* ea2 = (const float2*)ea;
    for (int rr = 0; rr < 16; rr++) {
        int r = w * 16 + rr;
        int nm = block0 + r;
        float2 xv = make_float2(0.f, 0.f);
        float2 av = make_float2(0.f, 0.f);
        if (nm < N_NODES) {
            xv = __ldg(&x2[(size_t)nm * 32 + lane]);
            int off0 = __ldg(&g_off[nm]);
            int off1 = __ldg(&g_off[nm + 1]);
            while (off0 < off1) {
                int n = min(off1 - off0, 32);
                int idl = (lane < n) ? __ldg(&g_eid[off0 + lane]) : 0;
#pragma unroll 4
                for (int j = 0; j < n; j++) {
                    int id = __shfl_sync(0xffffffffu, idl, j);
                    float2 v = __ldg(&ea2[(size_t)id * 32 + lane]);
                    av.x += v.x; av.y += v.y;
                }
                off0 += n;
            }
        }
        int c0 = 2 * lane;
        *(uint32_t*)(sh_hi + r * SW + c0)      = f2_to_h2(xv.x, xv.y);
        *(uint32_t*)(sh_lo + r * SW + c0)      = f2_to_h2(h_res(xv.x), h_res(xv.y));
        *(uint32_t*)(sh_hi + r * SW + 64 + c0) = f2_to_h2(av.x, av.y);
        *(uint32_t*)(sh_lo + r * SW + 64 + c0) = f2_to_h2(h_res(av.x), h_res(av.y));
    }
    __syncthreads();

    int warp_m = (w & 3) * 32;
    int wn = w >> 2;  // 0..1

    {
        float acc[2][8][4];
        gemm_layer<8, 16>(sh_hi, sh_lo, g_W0h, g_W0l, warp_m, wn * 8, lane, acc);
        epilogue_relu<8>(acc, b0, warp_m, wn * 8, lane, sh_hi, sh_lo);
        gemm_layer<8, 16>(sh_hi, sh_lo, g_W1h, g_W1l, warp_m, wn * 8, lane, acc);
        epilogue_relu<8>(acc, b1, warp_m, wn * 8, lane, sh_hi, sh_lo);
    }

    // layer 2: N = 64
    float* sy = (float*)smem_raw;  // 128 x 65 fp32 overlays sh_hi (written post-sync)
    {
        float acc2[2][4][4];
        gemm_layer<4, 8>(sh_hi, sh_lo, g_W2h, g_W2l, warp_m, wn * 4, lane, acc2);
        __syncthreads();  // everyone done reading h1 before overlay write
#pragma unroll
        for (int mt = 0; mt < 2; mt++)
#pragma unroll
            for (int nt = 0; nt < 4; nt++) {
                int r0 = warp_m + mt * 16 + (lane >> 2);
                int c  = (wn * 4 + nt) * 8 + (lane & 3) * 2;
                float bx = __ldg(&b2[c]), by = __ldg(&b2[c + 1]);
                sy[r0 * 65 + c]           = acc2[mt][nt][0] + bx;
                sy[r0 * 65 + c + 1]       = acc2[mt][nt][1] + by;
                sy[(r0 + 8) * 65 + c]     = acc2[mt][nt][2] + bx;
                sy[(r0 + 8) * 65 + c + 1] = acc2[mt][nt][3] + by;
            }
    }
    __syncthreads();

    // per-row LayerNorm stats
    if (tid < 128) {
        const float* row = sy + tid * 65;
        float s = 0.f, ss = 0.f;
#pragma unroll
        for (int c = 0; c < 64; c++) { float v = row[c]; s += v; ss += v * v; }
        float mu = s * 0.015625f;
        float var = ss * 0.015625f - mu * mu;
        s_stat[tid]       = mu;
        s_stat[128 + tid] = rsqrtf(var + 1e-5f);
    }
    __syncthreads();

    // coalesced normalize + residual + store
    for (int i = tid; i < 128 * 64; i += 256) {
        int r = i >> 6, c = i & 63;
        int nm = block0 + r;
        if (nm < N_NODES) {
            float v = sy[r * 65 + c];
            float res = (v - s_stat[r]) * s_stat[128 + r] * __ldg(&lng[c]) +
                        __ldg(&lnb[c]) + __ldg(&x[nm * 64 + c]);
            out[nm * 64 + c] = res;
        }
    }
}

// ---------------- launch ----------------
extern "C" void kernel_launch(void* const* d_in, const int* in_sizes, int n_in,
                              void* d_out, int out_size) {
    const float* x  = (const float*)d_in[0];
    const int*   ei = (const int*)d_in[1];   // int32 or int64; detected on device
    const float* ea = (const float*)d_in[2];
    const float* W0 = (const float*)d_in[3];
    const float* b0 = (const float*)d_in[4];
    const float* W1 = (const float*)d_in[5];
    const float* b1 = (const float*)d_in[6];
    const float* W2 = (const float*)d_in[7];
    const float* b2 = (const float*)d_in[8];
    const float* lg = (const float*)d_in[9];
    const float* lb = (const float*)d_in[10];
    float* out = (float*)d_out;

    // 1) zero histogram (first so ncu -s 5 lands on mlp_kernel)
    void* cntp = nullptr;
    cudaGetSymbolAddress(&cntp, g_count);
    cudaMemsetAsync(cntp, 0, sizeof(int) * N_NODES, 0);

    // 2) pack weights into split-fp16 mma fragments
    pack_w_kernel<<<40, 256>>>(W0, W1, W2);

    // 3) CSR build: histogram -> scan -> bucket scatter of edge ids
    hist_kernel<<<(N_EDGES + 511) / 512, 512>>>(ei);
    scan_kernel<<<1, 1024>>>();
    bucket_kernel<<<(N_EDGES + 511) / 512, 512>>>(ei);

    // 4) fused gather + MLP + LN + residual
    const int smem_bytes = 2 * 128 * SW * (int)sizeof(__half) + 256 * (int)sizeof(float);
    cudaFuncSetAttribute(mlp_kernel, cudaFuncAttributeMaxDynamicSharedMemorySize, smem_bytes);
    int grid = (N_NODES + TILE_M - 1) / TILE_M;
    mlp_kernel<<<grid, 256, smem_bytes>>>(x, ea, b0, b1, b2, lg, lb, out);
}

// round 4
// speedup vs baseline: 1.3585x; 1.3585x over previous
#include <cuda_runtime.h>
#include <cuda_fp16.h>
#include <cstdint>

#define N_NODES 100000
#define N_EDGES 1200000
#define D_NODE 64
#define HID 128
#define SW 136            // smem row stride in halfs (pad -> conflict-free mma frag loads)
#define TILE_M 128

// ---------------- device scratch (no allocs allowed) ----------------
__device__ float g_agg[(size_t)N_NODES * 64];   // 25.6 MB, written by gather (no memset needed)
__device__ int g_count[N_NODES];                // per-dest edge counts (zeroed by memset)
__device__ int g_off[N_NODES + 1];              // CSR offsets
__device__ int g_cursor[N_NODES];               // fill cursors (init = offsets, by scan kernel)
__device__ int g_eid[N_EDGES];                  // edge ids sorted by destination
// packed fp16 weight fragments (hi + lo split): [kt][ntile][lane] -> uint2 (b0,b1 of m16n8k16 B frag)
__device__ uint2 g_W0h[8 * 16 * 32], g_W0l[8 * 16 * 32];
__device__ uint2 g_W1h[8 * 16 * 32], g_W1l[8 * 16 * 32];
__device__ uint2 g_W2h[8 *  8 * 32], g_W2l[8 *  8 * 32];

// ---------------- helpers ----------------
__device__ __forceinline__ uint32_t f2_to_h2(float a, float b) {
    __half ha = __float2half_rn(a), hb = __float2half_rn(b);
    return (uint32_t)__half_as_ushort(ha) | ((uint32_t)__half_as_ushort(hb) << 16);
}
__device__ __forceinline__ float h_res(float a) {
    return a - __half2float(__float2half_rn(a));
}
__device__ __forceinline__ bool detect_i64(const int* ei) {
    // int64 layout => odd int32 words of first values (<100000, nonneg) are zero
    return (ei[1] == 0) & (ei[3] == 0) & (ei[5] == 0) & (ei[7] == 0);
}
__device__ __forceinline__ int dest_of(const int* ei, int e, bool is64) {
    if (is64) return (int)((const long long*)ei)[N_EDGES + e];
    return ei[N_EDGES + e];
}

__device__ __forceinline__ void mma16816(float c[4], const uint32_t a[4], uint2 b) {
    asm volatile(
        "mma.sync.aligned.m16n8k16.row.col.f32.f16.f16.f32 "
        "{%0,%1,%2,%3},{%4,%5,%6,%7},{%8,%9},{%0,%1,%2,%3};"
        : "+f"(c[0]), "+f"(c[1]), "+f"(c[2]), "+f"(c[3])
        : "r"(a[0]), "r"(a[1]), "r"(a[2]), "r"(a[3]), "r"(b.x), "r"(b.y));
}

// ---------------- weight pack: fp32 -> (hi, lo) fp16 mma B fragments ----------------
__global__ void pack_w_kernel(const float* __restrict__ W0,
                              const float* __restrict__ W1,
                              const float* __restrict__ W2) {
    int t = blockIdx.x * blockDim.x + threadIdx.x;
    if (t >= 10240) return;
    const float* W; uint2 *ph, *pl; int NT, Ncols, idx;
    if (t < 4096)       { W = W0; ph = g_W0h; pl = g_W0l; NT = 16; Ncols = 128; idx = t; }
    else if (t < 8192)  { W = W1; ph = g_W1h; pl = g_W1l; NT = 16; Ncols = 128; idx = t - 4096; }
    else                { W = W2; ph = g_W2h; pl = g_W2l; NT = 8;  Ncols = 64;  idx = t - 8192; }
    int lane = idx & 31, tile = idx >> 5;
    int nt = tile % NT, kt = tile / NT;
    int k0 = kt * 16 + (lane & 3) * 2;
    int n  = nt * 8  + (lane >> 2);
    float w00 = W[(k0    ) * Ncols + n];
    float w01 = W[(k0 + 1) * Ncols + n];
    float w10 = W[(k0 + 8) * Ncols + n];
    float w11 = W[(k0 + 9) * Ncols + n];
    ph[idx] = make_uint2(f2_to_h2(w00, w01), f2_to_h2(w10, w11));
    pl[idx] = make_uint2(f2_to_h2(h_res(w00), h_res(w01)), f2_to_h2(h_res(w10), h_res(w11)));
}

// ---------------- CSR build: histogram -> scan -> bucket scatter ----------------
__global__ void hist_kernel(const int* __restrict__ ei) {
    bool is64 = detect_i64(ei);
    int e = blockIdx.x * blockDim.x + threadIdx.x;
    if (e >= N_EDGES) return;
    atomicAdd(&g_count[dest_of(ei, e, is64)], 1);
}

__global__ __launch_bounds__(1024) void scan_kernel() {
    __shared__ int s_warp[32];
    const int t = threadIdx.x, lane = t & 31, wid = t >> 5;
    const int CH = (N_NODES + 1023) / 1024;  // 98
    int beg = t * CH;
    int end = min(beg + CH, N_NODES);
    int s = 0;
    for (int i = beg; i < end; i++) s += g_count[i];
    // inclusive warp scan of per-thread sums
    int x = s;
#pragma unroll
    for (int d = 1; d < 32; d <<= 1) {
        int y = __shfl_up_sync(0xffffffffu, x, d);
        if (lane >= d) x += y;
    }
    if (lane == 31) s_warp[wid] = x;
    __syncthreads();
    if (wid == 0) {
        int wv = s_warp[lane];
#pragma unroll
        for (int d = 1; d < 32; d <<= 1) {
            int y = __shfl_up_sync(0xffffffffu, wv, d);
            if (lane >= d) wv += y;
        }
        s_warp[lane] = wv - s_warp[lane];  // exclusive warp base
    }
    __syncthreads();
    int base = (x - s) + s_warp[wid];      // exclusive prefix for this thread
    int run = base;
    for (int i = beg; i < end; i++) {
        int c = g_count[i];
        g_off[i] = run;
        g_cursor[i] = run;
        run += c;
    }
    if (t == 1023) g_off[N_NODES] = run;   // last chunk empty -> run == total
}

__global__ void bucket_kernel(const int* __restrict__ ei) {
    bool is64 = detect_i64(ei);
    int e = blockIdx.x * blockDim.x + threadIdx.x;
    if (e >= N_EDGES) return;
    int d = dest_of(ei, e, is64);
    int pos = atomicAdd(&g_cursor[d], 1);
    g_eid[pos] = e;
}

// ---------------- gather: one warp per node, segment-sum via CSR ----------------
__global__ __launch_bounds__(256) void gather_kernel(const float2* __restrict__ ea2) {
    int w = (blockIdx.x * blockDim.x + threadIdx.x) >> 5;
    int lane = threadIdx.x & 31;
    if (w >= N_NODES) return;
    int i    = __ldg(&g_off[w]);
    int endo = __ldg(&g_off[w + 1]);
    float sx = 0.f, sy = 0.f;
    // 4-wide unrolled: 4 independent 256B row loads in flight per warp
    for (; i + 4 <= endo; i += 4) {
        int e0 = __ldg(&g_eid[i]);
        int e1 = __ldg(&g_eid[i + 1]);
        int e2 = __ldg(&g_eid[i + 2]);
        int e3 = __ldg(&g_eid[i + 3]);
        float2 v0 = __ldg(&ea2[(size_t)e0 * 32 + lane]);
        float2 v1 = __ldg(&ea2[(size_t)e1 * 32 + lane]);
        float2 v2 = __ldg(&ea2[(size_t)e2 * 32 + lane]);
        float2 v3 = __ldg(&ea2[(size_t)e3 * 32 + lane]);
        sx += (v0.x + v1.x) + (v2.x + v3.x);
        sy += (v0.y + v1.y) + (v2.y + v3.y);
    }
    for (; i < endo; i++) {
        int e = __ldg(&g_eid[i]);
        float2 v = __ldg(&ea2[(size_t)e * 32 + lane]);
        sx += v.x; sy += v.y;
    }
    ((float2*)g_agg)[(size_t)w * 32 + lane] = make_float2(sx, sy);
}

// ---------------- fused MLP + LayerNorm + residual ----------------
template <int NTW, int NTT>
__device__ __forceinline__ void gemm_layer(const __half* sh_hi, const __half* sh_lo,
                                           const uint2* __restrict__ Bh,
                                           const uint2* __restrict__ Bl,
                                           int warp_m, int ntile0, int lane,
                                           float acc[2][NTW][4]) {
#pragma unroll
    for (int mt = 0; mt < 2; mt++)
#pragma unroll
        for (int nt = 0; nt < NTW; nt++)
#pragma unroll
            for (int q = 0; q < 4; q++) acc[mt][nt][q] = 0.f;

    int rA  = warp_m + (lane >> 2);
    int cAq = (lane & 3) * 2;
#pragma unroll
    for (int kt = 0; kt < 8; kt++) {
        uint32_t Ah[2][4], Al[2][4];
        int cA = kt * 16 + cAq;
#pragma unroll
        for (int mt = 0; mt < 2; mt++) {
            int r = rA + mt * 16;
            Ah[mt][0] = *(const uint32_t*)(sh_hi + r * SW + cA);
            Ah[mt][1] = *(const uint32_t*)(sh_hi + (r + 8) * SW + cA);
            Ah[mt][2] = *(const uint32_t*)(sh_hi + r * SW + cA + 8);
            Ah[mt][3] = *(const uint32_t*)(sh_hi + (r + 8) * SW + cA + 8);
            Al[mt][0] = *(const uint32_t*)(sh_lo + r * SW + cA);
            Al[mt][1] = *(const uint32_t*)(sh_lo + (r + 8) * SW + cA);
            Al[mt][2] = *(const uint32_t*)(sh_lo + r * SW + cA + 8);
            Al[mt][3] = *(const uint32_t*)(sh_lo + (r + 8) * SW + cA + 8);
        }
#pragma unroll
        for (int nt = 0; nt < NTW; nt++) {
            int bi = (kt * NTT + ntile0 + nt) * 32 + lane;
            uint2 bh = __ldg(&Bh[bi]);
            uint2 bl = __ldg(&Bl[bi]);
#pragma unroll
            for (int mt = 0; mt < 2; mt++) {
                mma16816(acc[mt][nt], Ah[mt], bh);   // hi * hi
                mma16816(acc[mt][nt], Al[mt], bh);   // lo * hi
                mma16816(acc[mt][nt], Ah[mt], bl);   // hi * lo
            }
        }
    }
}

template <int NTW>
__device__ __forceinline__ void epilogue_relu(float acc[2][NTW][4],
                                              const float* __restrict__ bias,
                                              int warp_m, int ntile0, int lane,
                                              __half* sh_hi, __half* sh_lo) {
    __syncthreads();  // all warps done reading previous h
#pragma unroll
    for (int mt = 0; mt < 2; mt++)
#pragma unroll
        for (int nt = 0; nt < NTW; nt++) {
            int r0 = warp_m + mt * 16 + (lane >> 2);
            int c  = (ntile0 + nt) * 8 + (lane & 3) * 2;
            float bx = __ldg(&bias[c]), by = __ldg(&bias[c + 1]);
            float v0 = fmaxf(acc[mt][nt][0] + bx, 0.f);
            float v1 = fmaxf(acc[mt][nt][1] + by, 0.f);
            float v2 = fmaxf(acc[mt][nt][2] + bx, 0.f);
            float v3 = fmaxf(acc[mt][nt][3] + by, 0.f);
            *(uint32_t*)(sh_hi + r0 * SW + c)       = f2_to_h2(v0, v1);
            *(uint32_t*)(sh_lo + r0 * SW + c)       = f2_to_h2(h_res(v0), h_res(v1));
            *(uint32_t*)(sh_hi + (r0 + 8) * SW + c) = f2_to_h2(v2, v3);
            *(uint32_t*)(sh_lo + (r0 + 8) * SW + c) = f2_to_h2(h_res(v2), h_res(v3));
        }
    __syncthreads();
}

__global__ __launch_bounds__(256) void mlp_kernel(
    const float* __restrict__ x,
    const float* __restrict__ b0, const float* __restrict__ b1,
    const float* __restrict__ b2,
    const float* __restrict__ lng, const float* __restrict__ lnb,
    float* __restrict__ out) {
    extern __shared__ __align__(16) unsigned char smem_raw[];
    __half* sh_hi = (__half*)smem_raw;
    __half* sh_lo = sh_hi + 128 * SW;
    float*  s_stat = (float*)(sh_lo + 128 * SW);  // mu[128], rstd[128]

    int tid = threadIdx.x, lane = tid & 31, w = tid >> 5;
    int block0 = blockIdx.x * TILE_M;

    // stage h0 = [x | agg] as fp16 hi/lo
    for (int i = tid; i < 128 * 128; i += 256) {
        int r = i >> 7, c = i & 127;
        int nm = block0 + r;
        float v = 0.f;
        if (nm < N_NODES)
            v = (c < 64) ? __ldg(&x[nm * 64 + c]) : g_agg[nm * 64 + (c - 64)];
        __half hi = __float2half_rn(v);
        sh_hi[r * SW + c] = hi;
        sh_lo[r * SW + c] = __float2half_rn(v - __half2float(hi));
    }
    __syncthreads();

    int warp_m = (w & 3) * 32;
    int wn = w >> 2;  // 0..1

    {
        float acc[2][8][4];
        gemm_layer<8, 16>(sh_hi, sh_lo, g_W0h, g_W0l, warp_m, wn * 8, lane, acc);
        epilogue_relu<8>(acc, b0, warp_m, wn * 8, lane, sh_hi, sh_lo);
        gemm_layer<8, 16>(sh_hi, sh_lo, g_W1h, g_W1l, warp_m, wn * 8, lane, acc);
        epilogue_relu<8>(acc, b1, warp_m, wn * 8, lane, sh_hi, sh_lo);
    }

    // layer 2: N = 64
    float* sy = (float*)smem_raw;  // 128 x 65 fp32 overlays sh_hi (written post-sync)
    {
        float acc2[2][4][4];
        gemm_layer<4, 8>(sh_hi, sh_lo, g_W2h, g_W2l, warp_m, wn * 4, lane, acc2);
        __syncthreads();  // everyone done reading h1 before overlay write
#pragma unroll
        for (int mt = 0; mt < 2; mt++)
#pragma unroll
            for (int nt = 0; nt < 4; nt++) {
                int r0 = warp_m + mt * 16 + (lane >> 2);
                int c  = (wn * 4 + nt) * 8 + (lane & 3) * 2;
                float bx = __ldg(&b2[c]), by = __ldg(&b2[c + 1]);
                sy[r0 * 65 + c]           = acc2[mt][nt][0] + bx;
                sy[r0 * 65 + c + 1]       = acc2[mt][nt][1] + by;
                sy[(r0 + 8) * 65 + c]     = acc2[mt][nt][2] + bx;
                sy[(r0 + 8) * 65 + c + 1] = acc2[mt][nt][3] + by;
            }
    }
    __syncthreads();

    // per-row LayerNorm stats
    if (tid < 128) {
        const float* row = sy + tid * 65;
        float s = 0.f, ss = 0.f;
#pragma unroll
        for (int c = 0; c < 64; c++) { float v = row[c]; s += v; ss += v * v; }
        float mu = s * 0.015625f;
        float var = ss * 0.015625f - mu * mu;
        s_stat[tid]       = mu;
        s_stat[128 + tid] = rsqrtf(var + 1e-5f);
    }
    __syncthreads();

    // coalesced normalize + residual + store
    for (int i = tid; i < 128 * 64; i += 256) {
        int r = i >> 6, c = i & 63;
        int nm = block0 + r;
        if (nm < N_NODES) {
            float v = sy[r * 65 + c];
            float res = (v - s_stat[r]) * s_stat[128 + r] * __ldg(&lng[c]) +
                        __ldg(&lnb[c]) + __ldg(&x[nm * 64 + c]);
            out[nm * 64 + c] = res;
        }
    }
}

// ---------------- launch ----------------
extern "C" void kernel_launch(void* const* d_in, const int* in_sizes, int n_in,
                              void* d_out, int out_size) {
    const float* x  = (const float*)d_in[0];
    const int*   ei = (const int*)d_in[1];   // int32 or int64; detected on device
    const float* ea = (const float*)d_in[2];
    const float* W0 = (const float*)d_in[3];
    const float* b0 = (const float*)d_in[4];
    const float* W1 = (const float*)d_in[5];
    const float* b1 = (const float*)d_in[6];
    const float* W2 = (const float*)d_in[7];
    const float* b2 = (const float*)d_in[8];
    const float* lg = (const float*)d_in[9];
    const float* lb = (const float*)d_in[10];
    float* out = (float*)d_out;

    // 1) zero histogram
    void* cntp = nullptr;
    cudaGetSymbolAddress(&cntp, g_count);
    cudaMemsetAsync(cntp, 0, sizeof(int) * N_NODES, 0);

    // 2) pack weights into split-fp16 mma fragments
    pack_w_kernel<<<40, 256>>>(W0, W1, W2);

    // 3) CSR build: histogram -> scan -> bucket scatter of edge ids
    hist_kernel<<<(N_EDGES + 511) / 512, 512>>>(ei);
    scan_kernel<<<1, 1024>>>();
    bucket_kernel<<<(N_EDGES + 511) / 512, 512>>>(ei);

    // 4) gather: one warp per node, no atomics, full occupancy
    gather_kernel<<<(N_NODES * 32 + 255) / 256, 256>>>((const float2*)ea);

    // 5) fused MLP + LN + residual
    const int smem_bytes = 2 * 128 * SW * (int)sizeof(__half) + 256 * (int)sizeof(float);
    cudaFuncSetAttribute(mlp_kernel, cudaFuncAttributeMaxDynamicSharedMemorySize, smem_bytes);
    int grid = (N_NODES + TILE_M - 1) / TILE_M;
    mlp_kernel<<<grid, 256, smem_bytes>>>(x, b0, b1, b2, lg, lb, out);
}

// round 5
// speedup vs baseline: 1.6343x; 1.2030x over previous
#include <cuda_runtime.h>
#include <cuda_fp16.h>
#include <cstdint>

#define N_NODES 100000
#define N_EDGES 1200000
#define D_NODE 64
#define HID 128
#define SW 136            // smem row stride in halfs (pad -> conflict-free mma frag loads)
#define TILE_M 128

// ---------------- device scratch (no allocs allowed) ----------------
__device__ float g_agg[(size_t)N_NODES * 64];   // 25.6 MB, fully written by gather
__device__ int g_count[N_NODES];                // per-dest edge counts (zeroed by memset)
__device__ int g_off[N_NODES + 1];              // CSR offsets
__device__ int g_cursor[N_NODES];               // fill cursors (init = offsets, by scan kernel)
__device__ int g_eid[N_EDGES];                  // edge ids sorted by destination
// packed fp16 weight fragments (hi + lo split): [kt][ntile][lane] -> uint2 (b0,b1 of m16n8k16 B frag)
__device__ uint2 g_W0h[8 * 16 * 32], g_W0l[8 * 16 * 32];
__device__ uint2 g_W1h[8 * 16 * 32], g_W1l[8 * 16 * 32];
__device__ uint2 g_W2h[8 *  8 * 32], g_W2l[8 *  8 * 32];

// ---------------- helpers ----------------
__device__ __forceinline__ uint32_t f2_to_h2(float a, float b) {
    __half ha = __float2half_rn(a), hb = __float2half_rn(b);
    return (uint32_t)__half_as_ushort(ha) | ((uint32_t)__half_as_ushort(hb) << 16);
}
__device__ __forceinline__ float h_res(float a) {
    return a - __half2float(__float2half_rn(a));
}
__device__ __forceinline__ bool detect_i64(const int* ei) {
    // int64 layout => odd int32 words of first values (<100000, nonneg) are zero
    return (ei[1] == 0) & (ei[3] == 0) & (ei[5] == 0) & (ei[7] == 0);
}
__device__ __forceinline__ int dest_of(const int* ei, int e, bool is64) {
    if (is64) return (int)((const long long*)ei)[N_EDGES + e];
    return ei[N_EDGES + e];
}

__device__ __forceinline__ void mma16816(float c[4], const uint32_t a[4], uint2 b) {
    asm volatile(
        "mma.sync.aligned.m16n8k16.row.col.f32.f16.f16.f32 "
        "{%0,%1,%2,%3},{%4,%5,%6,%7},{%8,%9},{%0,%1,%2,%3};"
        : "+f"(c[0]), "+f"(c[1]), "+f"(c[2]), "+f"(c[3])
        : "r"(a[0]), "r"(a[1]), "r"(a[2]), "r"(a[3]), "r"(b.x), "r"(b.y));
}

// ---------------- weight pack: fp32 -> (hi, lo) fp16 mma B fragments ----------------
__global__ void pack_w_kernel(const float* __restrict__ W0,
                              const float* __restrict__ W1,
                              const float* __restrict__ W2) {
    int t = blockIdx.x * blockDim.x + threadIdx.x;
    if (t >= 10240) return;
    const float* W; uint2 *ph, *pl; int NT, Ncols, idx;
    if (t < 4096)       { W = W0; ph = g_W0h; pl = g_W0l; NT = 16; Ncols = 128; idx = t; }
    else if (t < 8192)  { W = W1; ph = g_W1h; pl = g_W1l; NT = 16; Ncols = 128; idx = t - 4096; }
    else                { W = W2; ph = g_W2h; pl = g_W2l; NT = 8;  Ncols = 64;  idx = t - 8192; }
    int lane = idx & 31, tile = idx >> 5;
    int nt = tile % NT, kt = tile / NT;
    int k0 = kt * 16 + (lane & 3) * 2;
    int n  = nt * 8  + (lane >> 2);
    float w00 = W[(k0    ) * Ncols + n];
    float w01 = W[(k0 + 1) * Ncols + n];
    float w10 = W[(k0 + 8) * Ncols + n];
    float w11 = W[(k0 + 9) * Ncols + n];
    ph[idx] = make_uint2(f2_to_h2(w00, w01), f2_to_h2(w10, w11));
    pl[idx] = make_uint2(f2_to_h2(h_res(w00), h_res(w01)), f2_to_h2(h_res(w10), h_res(w11)));
}

// ---------------- CSR build: histogram -> scan -> bucket scatter ----------------
__global__ void hist_kernel(const int* __restrict__ ei) {
    bool is64 = detect_i64(ei);
    int e = blockIdx.x * blockDim.x + threadIdx.x;
    if (e >= N_EDGES) return;
    atomicAdd(&g_count[dest_of(ei, e, is64)], 1);
}

// Tiled coalesced single-block scan: 98 tiles of 1024 contiguous counts.
__global__ __launch_bounds__(1024) void scan_kernel() {
    __shared__ int s_tot[32];   // per-warp totals of current tile
    __shared__ int s_wx[32];    // exclusive warp prefixes
    __shared__ int s_blk;       // current tile total
    __shared__ int s_carry;     // running base across tiles
    const int tid = threadIdx.x, lane = tid & 31, wid = tid >> 5;
    if (tid == 0) s_carry = 0;
    __syncthreads();

    const int NTILE = (N_NODES + 1023) / 1024;  // 98
    for (int t = 0; t < NTILE; t++) {
        int i = t * 1024 + tid;
        int c = (i < N_NODES) ? g_count[i] : 0;   // coalesced
        // inclusive warp scan
        int x = c;
#pragma unroll
        for (int d = 1; d < 32; d <<= 1) {
            int y = __shfl_up_sync(0xffffffffu, x, d);
            if (lane >= d) x += y;
        }
        if (lane == 31) s_tot[wid] = x;
        __syncthreads();
        if (wid == 0) {
            int v = s_tot[lane];
            int inc = v;
#pragma unroll
            for (int d = 1; d < 32; d <<= 1) {
                int y = __shfl_up_sync(0xffffffffu, inc, d);
                if (lane >= d) inc += y;
            }
            s_wx[lane] = inc - v;                 // exclusive warp prefix
            if (lane == 31) s_blk = inc;          // tile total
        }
        __syncthreads();
        int excl = s_carry + s_wx[wid] + (x - c);
        if (i < N_NODES) {                        // coalesced stores
            g_off[i] = excl;
            g_cursor[i] = excl;
        }
        __syncthreads();                          // all reads of s_carry done
        if (tid == 0) s_carry += s_blk;
        __syncthreads();
    }
    if (tid == 0) g_off[N_NODES] = s_carry;       // == N_EDGES
}

__global__ void bucket_kernel(const int* __restrict__ ei) {
    bool is64 = detect_i64(ei);
    int e = blockIdx.x * blockDim.x + threadIdx.x;
    if (e >= N_EDGES) return;
    int d = dest_of(ei, e, is64);
    int pos = atomicAdd(&g_cursor[d], 1);
    g_eid[pos] = e;
}

// ---------------- gather: one warp per node, segment-sum via CSR ----------------
__global__ __launch_bounds__(256) void gather_kernel(const float2* __restrict__ ea2) {
    int w = (blockIdx.x * blockDim.x + threadIdx.x) >> 5;
    int lane = threadIdx.x & 31;
    if (w >= N_NODES) return;
    int i    = __ldg(&g_off[w]);
    int endo = __ldg(&g_off[w + 1]);
    float sx = 0.f, sy = 0.f;
    // 4-wide unrolled: 4 independent 256B row loads in flight per warp
    for (; i + 4 <= endo; i += 4) {
        int e0 = __ldg(&g_eid[i]);
        int e1 = __ldg(&g_eid[i + 1]);
        int e2 = __ldg(&g_eid[i + 2]);
        int e3 = __ldg(&g_eid[i + 3]);
        float2 v0 = __ldg(&ea2[(size_t)e0 * 32 + lane]);
        float2 v1 = __ldg(&ea2[(size_t)e1 * 32 + lane]);
        float2 v2 = __ldg(&ea2[(size_t)e2 * 32 + lane]);
        float2 v3 = __ldg(&ea2[(size_t)e3 * 32 + lane]);
        sx += (v0.x + v1.x) + (v2.x + v3.x);
        sy += (v0.y + v1.y) + (v2.y + v3.y);
    }
    for (; i < endo; i++) {
        int e = __ldg(&g_eid[i]);
        float2 v = __ldg(&ea2[(size_t)e * 32 + lane]);
        sx += v.x; sy += v.y;
    }
    ((float2*)g_agg)[(size_t)w * 32 + lane] = make_float2(sx, sy);
}

// ---------------- fused MLP + LayerNorm + residual ----------------
template <int NTW, int NTT>
__device__ __forceinline__ void gemm_layer(const __half* sh_hi, const __half* sh_lo,
                                           const uint2* __restrict__ Bh,
                                           const uint2* __restrict__ Bl,
                                           int warp_m, int ntile0, int lane,
                                           float acc[2][NTW][4]) {
#pragma unroll
    for (int mt = 0; mt < 2; mt++)
#pragma unroll
        for (int nt = 0; nt < NTW; nt++)
#pragma unroll
            for (int q = 0; q < 4; q++) acc[mt][nt][q] = 0.f;

    int rA  = warp_m + (lane >> 2);
    int cAq = (lane & 3) * 2;
#pragma unroll
    for (int kt = 0; kt < 8; kt++) {
        uint32_t Ah[2][4], Al[2][4];
        int cA = kt * 16 + cAq;
#pragma unroll
        for (int mt = 0; mt < 2; mt++) {
            int r = rA + mt * 16;
            Ah[mt][0] = *(const uint32_t*)(sh_hi + r * SW + cA);
            Ah[mt][1] = *(const uint32_t*)(sh_hi + (r + 8) * SW + cA);
            Ah[mt][2] = *(const uint32_t*)(sh_hi + r * SW + cA + 8);
            Ah[mt][3] = *(const uint32_t*)(sh_hi + (r + 8) * SW + cA + 8);
            Al[mt][0] = *(const uint32_t*)(sh_lo + r * SW + cA);
            Al[mt][1] = *(const uint32_t*)(sh_lo + (r + 8) * SW + cA);
            Al[mt][2] = *(const uint32_t*)(sh_lo + r * SW + cA + 8);
            Al[mt][3] = *(const uint32_t*)(sh_lo + (r + 8) * SW + cA + 8);
        }
#pragma unroll
        for (int nt = 0; nt < NTW; nt++) {
            int bi = (kt * NTT + ntile0 + nt) * 32 + lane;
            uint2 bh = __ldg(&Bh[bi]);
            uint2 bl = __ldg(&Bl[bi]);
#pragma unroll
            for (int mt = 0; mt < 2; mt++) {
                mma16816(acc[mt][nt], Ah[mt], bh);   // hi * hi
                mma16816(acc[mt][nt], Al[mt], bh);   // lo * hi
                mma16816(acc[mt][nt], Ah[mt], bl);   // hi * lo
            }
        }
    }
}

template <int NTW>
__device__ __forceinline__ void epilogue_relu(float acc[2][NTW][4],
                                              const float* __restrict__ bias,
                                              int warp_m, int ntile0, int lane,
                                              __half* sh_hi, __half* sh_lo) {
    __syncthreads();  // all warps done reading previous h
#pragma unroll
    for (int mt = 0; mt < 2; mt++)
#pragma unroll
        for (int nt = 0; nt < NTW; nt++) {
            int r0 = warp_m + mt * 16 + (lane >> 2);
            int c  = (ntile0 + nt) * 8 + (lane & 3) * 2;
            float bx = __ldg(&bias[c]), by = __ldg(&bias[c + 1]);
            float v0 = fmaxf(acc[mt][nt][0] + bx, 0.f);
            float v1 = fmaxf(acc[mt][nt][1] + by, 0.f);
            float v2 = fmaxf(acc[mt][nt][2] + bx, 0.f);
            float v3 = fmaxf(acc[mt][nt][3] + by, 0.f);
            *(uint32_t*)(sh_hi + r0 * SW + c)       = f2_to_h2(v0, v1);
            *(uint32_t*)(sh_lo + r0 * SW + c)       = f2_to_h2(h_res(v0), h_res(v1));
            *(uint32_t*)(sh_hi + (r0 + 8) * SW + c) = f2_to_h2(v2, v3);
            *(uint32_t*)(sh_lo + (r0 + 8) * SW + c) = f2_to_h2(h_res(v2), h_res(v3));
        }
    __syncthreads();
}

__global__ __launch_bounds__(256) void mlp_kernel(
    const float* __restrict__ x,
    const float* __restrict__ b0, const float* __restrict__ b1,
    const float* __restrict__ b2,
    const float* __restrict__ lng, const float* __restrict__ lnb,
    float* __restrict__ out) {
    extern __shared__ __align__(16) unsigned char smem_raw[];
    __half* sh_hi = (__half*)smem_raw;
    __half* sh_lo = sh_hi + 128 * SW;
    float*  s_stat = (float*)(sh_lo + 128 * SW);  // mu[128], rstd[128]

    int tid = threadIdx.x, lane = tid & 31, w = tid >> 5;
    int block0 = blockIdx.x * TILE_M;

    // stage h0 = [x | agg] as fp16 hi/lo
    for (int i = tid; i < 128 * 128; i += 256) {
        int r = i >> 7, c = i & 127;
        int nm = block0 + r;
        float v = 0.f;
        if (nm < N_NODES)
            v = (c < 64) ? __ldg(&x[nm * 64 + c]) : g_agg[nm * 64 + (c - 64)];
        __half hi = __float2half_rn(v);
        sh_hi[r * SW + c] = hi;
        sh_lo[r * SW + c] = __float2half_rn(v - __half2float(hi));
    }
    __syncthreads();

    int warp_m = (w & 3) * 32;
    int wn = w >> 2;  // 0..1

    {
        float acc[2][8][4];
        gemm_layer<8, 16>(sh_hi, sh_lo, g_W0h, g_W0l, warp_m, wn * 8, lane, acc);
        epilogue_relu<8>(acc, b0, warp_m, wn * 8, lane, sh_hi, sh_lo);
        gemm_layer<8, 16>(sh_hi, sh_lo, g_W1h, g_W1l, warp_m, wn * 8, lane, acc);
        epilogue_relu<8>(acc, b1, warp_m, wn * 8, lane, sh_hi, sh_lo);
    }

    // layer 2: N = 64
    float* sy = (float*)smem_raw;  // 128 x 65 fp32 overlays sh_hi (written post-sync)
    {
        float acc2[2][4][4];
        gemm_layer<4, 8>(sh_hi, sh_lo, g_W2h, g_W2l, warp_m, wn * 4, lane, acc2);
        __syncthreads();  // everyone done reading h1 before overlay write
#pragma unroll
        for (int mt = 0; mt < 2; mt++)
#pragma unroll
            for (int nt = 0; nt < 4; nt++) {
                int r0 = warp_m + mt * 16 + (lane >> 2);
                int c  = (wn * 4 + nt) * 8 + (lane & 3) * 2;
                float bx = __ldg(&b2[c]), by = __ldg(&b2[c + 1]);
                sy[r0 * 65 + c]           = acc2[mt][nt][0] + bx;
                sy[r0 * 65 + c + 1]       = acc2[mt][nt][1] + by;
                sy[(r0 + 8) * 65 + c]     = acc2[mt][nt][2] + bx;
                sy[(r0 + 8) * 65 + c + 1] = acc2[mt][nt][3] + by;
            }
    }
    __syncthreads();

    // per-row LayerNorm stats
    if (tid < 128) {
        const float* row = sy + tid * 65;
        float s = 0.f, ss = 0.f;
#pragma unroll
        for (int c = 0; c < 64; c++) { float v = row[c]; s += v; ss += v * v; }
        float mu = s * 0.015625f;
        float var = ss * 0.015625f - mu * mu;
        s_stat[tid]       = mu;
        s_stat[128 + tid] = rsqrtf(var + 1e-5f);
    }
    __syncthreads();

    // coalesced normalize + residual + store
    for (int i = tid; i < 128 * 64; i += 256) {
        int r = i >> 6, c = i & 63;
        int nm = block0 + r;
        if (nm < N_NODES) {
            float v = sy[r * 65 + c];
            float res = (v - s_stat[r]) * s_stat[128 + r] * __ldg(&lng[c]) +
                        __ldg(&lnb[c]) + __ldg(&x[nm * 64 + c]);
            out[nm * 64 + c] = res;
        }
    }
}

// ---------------- launch ----------------
extern "C" void kernel_launch(void* const* d_in, const int* in_sizes, int n_in,
                              void* d_out, int out_size) {
    const float* x  = (const float*)d_in[0];
    const int*   ei = (const int*)d_in[1];   // int32 or int64; detected on device
    const float* ea = (const float*)d_in[2];
    const float* W0 = (const float*)d_in[3];
    const float* b0 = (const float*)d_in[4];
    const float* W1 = (const float*)d_in[5];
    const float* b1 = (const float*)d_in[6];
    const float* W2 = (const float*)d_in[7];
    const float* b2 = (const float*)d_in[8];
    const float* lg = (const float*)d_in[9];
    const float* lb = (const float*)d_in[10];
    float* out = (float*)d_out;

    // 1) zero histogram
    void* cntp = nullptr;
    cudaGetSymbolAddress(&cntp, g_count);
    cudaMemsetAsync(cntp, 0, sizeof(int) * N_NODES, 0);

    // 2) pack weights into split-fp16 mma fragments
    pack_w_kernel<<<40, 256>>>(W0, W1, W2);

    // 3) CSR build: histogram -> coalesced tiled scan -> bucket scatter
    hist_kernel<<<(N_EDGES + 511) / 512, 512>>>(ei);
    scan_kernel<<<1, 1024>>>();
    bucket_kernel<<<(N_EDGES + 511) / 512, 512>>>(ei);

    // 4) gather: one warp per node, no atomics, full occupancy
    gather_kernel<<<(N_NODES * 32 + 255) / 256, 256>>>((const float2*)ea);

    // 5) fused MLP + LN + residual
    const int smem_bytes = 2 * 128 * SW * (int)sizeof(__half) + 256 * (int)sizeof(float);
    cudaFuncSetAttribute(mlp_kernel, cudaFuncAttributeMaxDynamicSharedMemorySize, smem_bytes);
    int grid = (N_NODES + TILE_M - 1) / TILE_M;
    mlp_kernel<<<grid, 256, smem_bytes>>>(x, b0, b1, b2, lg, lb, out);
}

// round 6
// speedup vs baseline: 2.7148x; 1.6611x over previous
#include <cuda_runtime.h>
#include <cuda_fp16.h>
#include <cstdint>

#define N_NODES 100000
#define N_EDGES 1200000
#define D_NODE 64
#define HID 128
#define SW 136            // smem row stride in halfs (pad -> conflict-free mma frag loads)
#define TILE_M 128

// ---------------- device scratch (no allocs allowed) ----------------
__device__ float g_agg[(size_t)N_NODES * 64];   // 25.6 MB, fully written by gather
__device__ int g_count[N_NODES];                // zero-init at load; scan re-zeroes after use
__device__ int g_off[N_NODES + 1];              // CSR offsets
__device__ int g_cursor[N_NODES];               // fill cursors (init = offsets, by scan kernel)
__device__ int g_eid[N_EDGES];                  // edge ids sorted by destination
// packed fp16 weight fragments (hi + lo split): [kt][ntile][lane] -> uint2 (b0,b1 of m16n8k16 B frag)
__device__ uint2 g_W0h[8 * 16 * 32], g_W0l[8 * 16 * 32];
__device__ uint2 g_W1h[8 * 16 * 32], g_W1l[8 * 16 * 32];
__device__ uint2 g_W2h[8 *  8 * 32], g_W2l[8 *  8 * 32];

// ---------------- helpers ----------------
__device__ __forceinline__ uint32_t f2_to_h2(float a, float b) {
    __half ha = __float2half_rn(a), hb = __float2half_rn(b);
    return (uint32_t)__half_as_ushort(ha) | ((uint32_t)__half_as_ushort(hb) << 16);
}
__device__ __forceinline__ float h_res(float a) {
    return a - __half2float(__float2half_rn(a));
}
__device__ __forceinline__ bool detect_i64(const int* ei) {
    // int64 layout => odd int32 words of first values (<100000, nonneg) are zero
    return (ei[1] == 0) & (ei[3] == 0) & (ei[5] == 0) & (ei[7] == 0);
}
__device__ __forceinline__ int dest_of(const int* ei, int e, bool is64) {
    if (is64) return (int)((const long long*)ei)[N_EDGES + e];
    return ei[N_EDGES + e];
}

__device__ __forceinline__ void mma16816(float c[4], const uint32_t a[4], uint2 b) {
    asm volatile(
        "mma.sync.aligned.m16n8k16.row.col.f32.f16.f16.f32 "
        "{%0,%1,%2,%3},{%4,%5,%6,%7},{%8,%9},{%0,%1,%2,%3};"
        : "+f"(c[0]), "+f"(c[1]), "+f"(c[2]), "+f"(c[3])
        : "r"(a[0]), "r"(a[1]), "r"(a[2]), "r"(a[3]), "r"(b.x), "r"(b.y));
}

// ---------------- CSR build ----------------
__global__ void hist_kernel(const int* __restrict__ ei) {
    bool is64 = detect_i64(ei);
    int e = blockIdx.x * blockDim.x + threadIdx.x;
    if (e >= N_EDGES) return;
    atomicAdd(&g_count[dest_of(ei, e, is64)], 1);
}

// Tiled coalesced single-block scan; also re-zeroes g_count (last consumer)
// so no memset launch is needed and the per-replay invariant holds.
__global__ __launch_bounds__(1024) void scan_kernel() {
    __shared__ int s_tot[32];   // per-warp totals of current tile
    __shared__ int s_wx[32];    // exclusive warp prefixes
    __shared__ int s_blk;       // current tile total
    __shared__ int s_carry;     // running base across tiles
    const int tid = threadIdx.x, lane = tid & 31, wid = tid >> 5;
    if (tid == 0) s_carry = 0;
    __syncthreads();

    const int NTILE = (N_NODES + 1023) / 1024;  // 98
    for (int t = 0; t < NTILE; t++) {
        int i = t * 1024 + tid;
        int c = (i < N_NODES) ? g_count[i] : 0;   // coalesced
        // inclusive warp scan
        int x = c;
#pragma unroll
        for (int d = 1; d < 32; d <<= 1) {
            int y = __shfl_up_sync(0xffffffffu, x, d);
            if (lane >= d) x += y;
        }
        if (lane == 31) s_tot[wid] = x;
        __syncthreads();
        if (wid == 0) {
            int v = s_tot[lane];
            int inc = v;
#pragma unroll
            for (int d = 1; d < 32; d <<= 1) {
                int y = __shfl_up_sync(0xffffffffu, inc, d);
                if (lane >= d) inc += y;
            }
            s_wx[lane] = inc - v;                 // exclusive warp prefix
            if (lane == 31) s_blk = inc;          // tile total
        }
        __syncthreads();
        int excl = s_carry + s_wx[wid] + (x - c);
        if (i < N_NODES) {                        // coalesced stores
            g_off[i] = excl;
            g_cursor[i] = excl;
            g_count[i] = 0;                       // reset for next replay
        }
        __syncthreads();                          // all reads of s_carry done
        if (tid == 0) s_carry += s_blk;
        __syncthreads();
    }
    if (tid == 0) g_off[N_NODES] = s_carry;       // == N_EDGES
}

// bucket scatter of edge ids; extra blocks at the end pack the weights
// (fold-in keeps the launch count at 5 so ncu's fixed skip lands on mlp_kernel).
#define NB_BUCKET ((N_EDGES + 511) / 512)
__global__ __launch_bounds__(512) void bucket_pack_kernel(
    const int* __restrict__ ei,
    const float* __restrict__ W0, const float* __restrict__ W1,
    const float* __restrict__ W2) {
    if (blockIdx.x < NB_BUCKET) {
        bool is64 = detect_i64(ei);
        int e = blockIdx.x * 512 + threadIdx.x;
        if (e >= N_EDGES) return;
        int d = dest_of(ei, e, is64);
        int pos = atomicAdd(&g_cursor[d], 1);
        g_eid[pos] = e;
        return;
    }
    // ---- pack: fp32 weights -> (hi, lo) fp16 mma B fragments ----
    int t = (blockIdx.x - NB_BUCKET) * 512 + threadIdx.x;
    if (t >= 10240) return;
    const float* W; uint2 *ph, *pl; int NT, Ncols, idx;
    if (t < 4096)       { W = W0; ph = g_W0h; pl = g_W0l; NT = 16; Ncols = 128; idx = t; }
    else if (t < 8192)  { W = W1; ph = g_W1h; pl = g_W1l; NT = 16; Ncols = 128; idx = t - 4096; }
    else                { W = W2; ph = g_W2h; pl = g_W2l; NT = 8;  Ncols = 64;  idx = t - 8192; }
    int lane = idx & 31, tile = idx >> 5;
    int nt = tile % NT, kt = tile / NT;
    int k0 = kt * 16 + (lane & 3) * 2;
    int n  = nt * 8  + (lane >> 2);
    float w00 = W[(k0    ) * Ncols + n];
    float w01 = W[(k0 + 1) * Ncols + n];
    float w10 = W[(k0 + 8) * Ncols + n];
    float w11 = W[(k0 + 9) * Ncols + n];
    ph[idx] = make_uint2(f2_to_h2(w00, w01), f2_to_h2(w10, w11));
    pl[idx] = make_uint2(f2_to_h2(h_res(w00), h_res(w01)), f2_to_h2(h_res(w10), h_res(w11)));
}

// ---------------- gather: one warp per node, 2 edges per LDG.128 ----------------
__global__ __launch_bounds__(256) void gather_kernel(const float4* __restrict__ ea4) {
    int w = (blockIdx.x * blockDim.x + threadIdx.x) >> 5;
    int lane = threadIdx.x & 31;
    if (w >= N_NODES) return;
    int half = lane >> 4, li = lane & 15;
    int i    = __ldg(&g_off[w]);
    int endo = __ldg(&g_off[w + 1]);
    float4 s = make_float4(0.f, 0.f, 0.f, 0.f);
    // 8 edges in flight: 4 independent LDG.128 per lane, 2 edges per load
    for (; i + 8 <= endo; i += 8) {
        int e0 = __ldg(&g_eid[i     + half]);
        int e1 = __ldg(&g_eid[i + 2 + half]);
        int e2 = __ldg(&g_eid[i + 4 + half]);
        int e3 = __ldg(&g_eid[i + 6 + half]);
        float4 v0 = __ldg(&ea4[(size_t)e0 * 16 + li]);
        float4 v1 = __ldg(&ea4[(size_t)e1 * 16 + li]);
        float4 v2 = __ldg(&ea4[(size_t)e2 * 16 + li]);
        float4 v3 = __ldg(&ea4[(size_t)e3 * 16 + li]);
        s.x += (v0.x + v1.x) + (v2.x + v3.x);
        s.y += (v0.y + v1.y) + (v2.y + v3.y);
        s.z += (v0.z + v1.z) + (v2.z + v3.z);
        s.w += (v0.w + v1.w) + (v2.w + v3.w);
    }
    for (; i + 2 <= endo; i += 2) {
        int e = __ldg(&g_eid[i + half]);
        float4 v = __ldg(&ea4[(size_t)e * 16 + li]);
        s.x += v.x; s.y += v.y; s.z += v.z; s.w += v.w;
    }
    if (i < endo && half == 0) {               // odd remainder: half 0 only
        int e = __ldg(&g_eid[i]);
        float4 v = __ldg(&ea4[(size_t)e * 16 + li]);
        s.x += v.x; s.y += v.y; s.z += v.z; s.w += v.w;
    }
    // merge the two half-warps
    s.x += __shfl_xor_sync(0xffffffffu, s.x, 16);
    s.y += __shfl_xor_sync(0xffffffffu, s.y, 16);
    s.z += __shfl_xor_sync(0xffffffffu, s.z, 16);
    s.w += __shfl_xor_sync(0xffffffffu, s.w, 16);
    if (half == 0)
        ((float4*)g_agg)[(size_t)w * 16 + li] = s;
}

// ---------------- fused MLP + LayerNorm + residual ----------------
template <int NTW, int NTT>
__device__ __forceinline__ void gemm_layer(const __half* sh_hi, const __half* sh_lo,
                                           const uint2* __restrict__ Bh,
                                           const uint2* __restrict__ Bl,
                                           int warp_m, int ntile0, int lane,
                                           float acc[2][NTW][4]) {
#pragma unroll
    for (int mt = 0; mt < 2; mt++)
#pragma unroll
        for (int nt = 0; nt < NTW; nt++)
#pragma unroll
            for (int q = 0; q < 4; q++) acc[mt][nt][q] = 0.f;

    int rA  = warp_m + (lane >> 2);
    int cAq = (lane & 3) * 2;
#pragma unroll
    for (int kt = 0; kt < 8; kt++) {
        uint32_t Ah[2][4], Al[2][4];
        int cA = kt * 16 + cAq;
#pragma unroll
        for (int mt = 0; mt < 2; mt++) {
            int r = rA + mt * 16;
            Ah[mt][0] = *(const uint32_t*)(sh_hi + r * SW + cA);
            Ah[mt][1] = *(const uint32_t*)(sh_hi + (r + 8) * SW + cA);
            Ah[mt][2] = *(const uint32_t*)(sh_hi + r * SW + cA + 8);
            Ah[mt][3] = *(const uint32_t*)(sh_hi + (r + 8) * SW + cA + 8);
            Al[mt][0] = *(const uint32_t*)(sh_lo + r * SW + cA);
            Al[mt][1] = *(const uint32_t*)(sh_lo + (r + 8) * SW + cA);
            Al[mt][2] = *(const uint32_t*)(sh_lo + r * SW + cA + 8);
            Al[mt][3] = *(const uint32_t*)(sh_lo + (r + 8) * SW + cA + 8);
        }
#pragma unroll
        for (int nt = 0; nt < NTW; nt++) {
            int bi = (kt * NTT + ntile0 + nt) * 32 + lane;
            uint2 bh = __ldg(&Bh[bi]);
            uint2 bl = __ldg(&Bl[bi]);
#pragma unroll
            for (int mt = 0; mt < 2; mt++) {
                mma16816(acc[mt][nt], Ah[mt], bh);   // hi * hi
                mma16816(acc[mt][nt], Al[mt], bh);   // lo * hi
                mma16816(acc[mt][nt], Ah[mt], bl);   // hi * lo
            }
        }
    }
}

template <int NTW>
__device__ __forceinline__ void epilogue_relu(float acc[2][NTW][4],
                                              const float* __restrict__ bias,
                                              int warp_m, int ntile0, int lane,
                                              __half* sh_hi, __half* sh_lo) {
    __syncthreads();  // all warps done reading previous h
#pragma unroll
    for (int mt = 0; mt < 2; mt++)
#pragma unroll
        for (int nt = 0; nt < NTW; nt++) {
            int r0 = warp_m + mt * 16 + (lane >> 2);
            int c  = (ntile0 + nt) * 8 + (lane & 3) * 2;
            float bx = __ldg(&bias[c]), by = __ldg(&bias[c + 1]);
            float v0 = fmaxf(acc[mt][nt][0] + bx, 0.f);
            float v1 = fmaxf(acc[mt][nt][1] + by, 0.f);
            float v2 = fmaxf(acc[mt][nt][2] + bx, 0.f);
            float v3 = fmaxf(acc[mt][nt][3] + by, 0.f);
            *(uint32_t*)(sh_hi + r0 * SW + c)       = f2_to_h2(v0, v1);
            *(uint32_t*)(sh_lo + r0 * SW + c)       = f2_to_h2(h_res(v0), h_res(v1));
            *(uint32_t*)(sh_hi + (r0 + 8) * SW + c) = f2_to_h2(v2, v3);
            *(uint32_t*)(sh_lo + (r0 + 8) * SW + c) = f2_to_h2(h_res(v2), h_res(v3));
        }
    __syncthreads();
}

__global__ __launch_bounds__(256, 2) void mlp_kernel(
    const float* __restrict__ x,
    const float* __restrict__ b0, const float* __restrict__ b1,
    const float* __restrict__ b2,
    const float* __restrict__ lng, const float* __restrict__ lnb,
    float* __restrict__ out) {
    extern __shared__ __align__(16) unsigned char smem_raw[];
    __half* sh_hi = (__half*)smem_raw;
    __half* sh_lo = sh_hi + 128 * SW;
    float*  s_stat = (float*)(sh_lo + 128 * SW);  // mu[128], rstd[128]

    int tid = threadIdx.x, lane = tid & 31, w = tid >> 5;
    int block0 = blockIdx.x * TILE_M;

    // stage h0 = [x | agg] as fp16 hi/lo (float4 loads)
    const float4* x4   = (const float4*)x;
    const float4* agg4 = (const float4*)g_agg;
    for (int i = tid; i < 128 * 32; i += 256) {
        int r = i >> 5, c4 = i & 31;
        int nm = block0 + r;
        float4 v = make_float4(0.f, 0.f, 0.f, 0.f);
        if (nm < N_NODES)
            v = (c4 < 16) ? __ldg(&x4[(size_t)nm * 16 + c4])
                          : __ldg(&agg4[(size_t)nm * 16 + (c4 - 16)]);
        int c = c4 * 4;
        *(uint32_t*)(sh_hi + r * SW + c)     = f2_to_h2(v.x, v.y);
        *(uint32_t*)(sh_hi + r * SW + c + 2) = f2_to_h2(v.z, v.w);
        *(uint32_t*)(sh_lo + r * SW + c)     = f2_to_h2(h_res(v.x), h_res(v.y));
        *(uint32_t*)(sh_lo + r * SW + c + 2) = f2_to_h2(h_res(v.z), h_res(v.w));
    }
    __syncthreads();

    int warp_m = (w & 3) * 32;
    int wn = w >> 2;  // 0..1

    {
        float acc[2][8][4];
        gemm_layer<8, 16>(sh_hi, sh_lo, g_W0h, g_W0l, warp_m, wn * 8, lane, acc);
        epilogue_relu<8>(acc, b0, warp_m, wn * 8, lane, sh_hi, sh_lo);
        gemm_layer<8, 16>(sh_hi, sh_lo, g_W1h, g_W1l, warp_m, wn * 8, lane, acc);
        epilogue_relu<8>(acc, b1, warp_m, wn * 8, lane, sh_hi, sh_lo);
    }

    // layer 2: N = 64
    float* sy = (float*)smem_raw;  // 128 x 65 fp32 overlays sh_hi (written post-sync)
    {
        float acc2[2][4][4];
        gemm_layer<4, 8>(sh_hi, sh_lo, g_W2h, g_W2l, warp_m, wn * 4, lane, acc2);
        __syncthreads();  // everyone done reading h1 before overlay write
#pragma unroll
        for (int mt = 0; mt < 2; mt++)
#pragma unroll
            for (int nt = 0; nt < 4; nt++) {
                int r0 = warp_m + mt * 16 + (lane >> 2);
                int c  = (wn * 4 + nt) * 8 + (lane & 3) * 2;
                float bx = __ldg(&b2[c]), by = __ldg(&b2[c + 1]);
                sy[r0 * 65 + c]           = acc2[mt][nt][0] + bx;
                sy[r0 * 65 + c + 1]       = acc2[mt][nt][1] + by;
                sy[(r0 + 8) * 65 + c]     = acc2[mt][nt][2] + bx;
                sy[(r0 + 8) * 65 + c + 1] = acc2[mt][nt][3] + by;
            }
    }
    __syncthreads();

    // per-row LayerNorm stats
    if (tid < 128) {
        const float* row = sy + tid * 65;
        float s = 0.f, ss = 0.f;
#pragma unroll
        for (int c = 0; c < 64; c++) { float v = row[c]; s += v; ss += v * v; }
        float mu = s * 0.015625f;
        float var = ss * 0.015625f - mu * mu;
        s_stat[tid]       = mu;
        s_stat[128 + tid] = rsqrtf(var + 1e-5f);
    }
    __syncthreads();

    // coalesced normalize + residual + store
    for (int i = tid; i < 128 * 64; i += 256) {
        int r = i >> 6, c = i & 63;
        int nm = block0 + r;
        if (nm < N_NODES) {
            float v = sy[r * 65 + c];
            float res = (v - s_stat[r]) * s_stat[128 + r] * __ldg(&lng[c]) +
                        __ldg(&lnb[c]) + __ldg(&x[nm * 64 + c]);
            out[nm * 64 + c] = res;
        }
    }
}

// ---------------- launch (exactly 5: hist, scan, bucket+pack, gather, mlp) ----------------
extern "C" void kernel_launch(void* const* d_in, const int* in_sizes, int n_in,
                              void* d_out, int out_size) {
    const float* x  = (const float*)d_in[0];
    const int*   ei = (const int*)d_in[1];   // int32 or int64; detected on device
    const float* ea = (const float*)d_in[2];
    const float* W0 = (const float*)d_in[3];
    const float* b0 = (const float*)d_in[4];
    const float* W1 = (const float*)d_in[5];
    const float* b1 = (const float*)d_in[6];
    const float* W2 = (const float*)d_in[7];
    const float* b2 = (const float*)d_in[8];
    const float* lg = (const float*)d_in[9];
    const float* lb = (const float*)d_in[10];
    float* out = (float*)d_out;

    // 0) histogram (g_count is zero: load-time init + scan re-zeroes each replay)
    hist_kernel<<<(N_EDGES + 511) / 512, 512>>>(ei);
    // 1) coalesced tiled scan (also resets g_count)
    scan_kernel<<<1, 1024>>>();
    // 2) bucket scatter of edge ids + weight packing (folded)
    bucket_pack_kernel<<<NB_BUCKET + 20, 512>>>(ei, W0, W1, W2);
    // 3) gather: one warp per node, 2 edges per LDG.128
    gather_kernel<<<(N_NODES * 32 + 255) / 256, 256>>>((const float4*)ea);
    // 4) fused MLP + LN + residual  (profiled position)
    const int smem_bytes = 2 * 128 * SW * (int)sizeof(__half) + 256 * (int)sizeof(float);
    cudaFuncSetAttribute(mlp_kernel, cudaFuncAttributeMaxDynamicSharedMemorySize, smem_bytes);
    int grid = (N_NODES + TILE_M - 1) / TILE_M;
    mlp_kernel<<<grid, 256, smem_bytes>>>(x, b0, b1, b2, lg, lb, out);
}

// round 7
// speedup vs baseline: 3.6738x; 1.3533x over previous
#include <cuda_runtime.h>
#include <cuda_fp16.h>
#include <cstdint>

#define N_NODES 100000
#define N_EDGES 1200000
#define D_NODE 64
#define HID 128
#define SW 136            // smem row stride in halfs (pad -> conflict-free mma/ldsm)
#define TILE_M 128

// ---------------- device scratch (no allocs allowed) ----------------
__device__ float g_agg[(size_t)N_NODES * 64];   // 25.6 MB, fully written by gather
__device__ int g_count[N_NODES];                // zero-init at load; scanA re-zeroes after use
__device__ int g_off[N_NODES + 1];              // CSR offsets
__device__ int g_cursor[N_NODES];               // fill cursors
__device__ int g_eid[N_EDGES];                  // edge ids sorted by destination
__device__ int g_bsum[128];                     // per-block sums for the parallel scan
// packed fp16 weight fragments (hi + lo split): [kt][ntile][lane] -> uint2 (b0,b1 of m16n8k16 B frag)
__device__ uint2 g_W0h[8 * 16 * 32], g_W0l[8 * 16 * 32];
__device__ uint2 g_W1h[8 * 16 * 32], g_W1l[8 * 16 * 32];
__device__ uint2 g_W2h[8 *  8 * 32], g_W2l[8 *  8 * 32];

// ---------------- helpers ----------------
__device__ __forceinline__ uint32_t f2_to_h2(float a, float b) {
    __half ha = __float2half_rn(a), hb = __float2half_rn(b);
    return (uint32_t)__half_as_ushort(ha) | ((uint32_t)__half_as_ushort(hb) << 16);
}
__device__ __forceinline__ float h_res(float a) {
    return a - __half2float(__float2half_rn(a));
}
__device__ __forceinline__ bool detect_i64(const int* ei) {
    return (ei[1] == 0) & (ei[3] == 0) & (ei[5] == 0) & (ei[7] == 0);
}
__device__ __forceinline__ int dest_of(const int* ei, int e, bool is64) {
    if (is64) return (int)((const long long*)ei)[N_EDGES + e];
    return ei[N_EDGES + e];
}

__device__ __forceinline__ void mma16816(float c[4], const uint32_t a[4], uint2 b) {
    asm volatile(
        "mma.sync.aligned.m16n8k16.row.col.f32.f16.f16.f32 "
        "{%0,%1,%2,%3},{%4,%5,%6,%7},{%8,%9},{%0,%1,%2,%3};"
        : "+f"(c[0]), "+f"(c[1]), "+f"(c[2]), "+f"(c[3])
        : "r"(a[0]), "r"(a[1]), "r"(a[2]), "r"(a[3]), "r"(b.x), "r"(b.y));
}

__device__ __forceinline__ void ldsm_x4(uint32_t a[4], const __half* p) {
    uint32_t addr = (uint32_t)__cvta_generic_to_shared(p);
    asm volatile("ldmatrix.sync.aligned.m8n8.x4.shared.b16 {%0,%1,%2,%3}, [%4];"
                 : "=r"(a[0]), "=r"(a[1]), "=r"(a[2]), "=r"(a[3]) : "r"(addr));
}

// ---------------- CSR build ----------------
__global__ void hist_kernel(const int* __restrict__ ei) {
    bool is64 = detect_i64(ei);
    int e = blockIdx.x * blockDim.x + threadIdx.x;
    if (e >= N_EDGES) return;
    atomicAdd(&g_count[dest_of(ei, e, is64)], 1);
}

#define NB_SCAN ((N_NODES + 1023) / 1024)   // 98

// Phase A: per-block local exclusive scan; writes local excl to g_off,
// block total to g_bsum, and re-zeroes g_count (per-replay invariant).
__global__ __launch_bounds__(1024) void scanA_kernel() {
    __shared__ int s_tot[32], s_wx[32];
    int b = blockIdx.x, tid = threadIdx.x, lane = tid & 31, wid = tid >> 5;
    int i = b * 1024 + tid;
    int c = (i < N_NODES) ? g_count[i] : 0;
    if (i < N_NODES) g_count[i] = 0;
    int x = c;
#pragma unroll
    for (int d = 1; d < 32; d <<= 1) {
        int y = __shfl_up_sync(0xffffffffu, x, d);
        if (lane >= d) x += y;
    }
    if (lane == 31) s_tot[wid] = x;
    __syncthreads();
    if (wid == 0) {
        int v = s_tot[lane];
        int inc = v;
#pragma unroll
        for (int d = 1; d < 32; d <<= 1) {
            int y = __shfl_up_sync(0xffffffffu, inc, d);
            if (lane >= d) inc += y;
        }
        s_wx[lane] = inc - v;
        if (lane == 31) g_bsum[b] = inc;   // block total
    }
    __syncthreads();
    if (i < N_NODES) g_off[i] = s_wx[wid] + (x - c);
}

// Phase B: 1 block scans the 98 block sums (exclusive), writes grand total.
__global__ __launch_bounds__(128) void scanB_kernel() {
    __shared__ int wsum[4];
    int tid = threadIdx.x, lane = tid & 31, wid = tid >> 5;
    int v = (tid < NB_SCAN) ? g_bsum[tid] : 0;
    int x = v;
#pragma unroll
    for (int d = 1; d < 32; d <<= 1) {
        int y = __shfl_up_sync(0xffffffffu, x, d);
        if (lane >= d) x += y;
    }
    if (lane == 31) wsum[wid] = x;
    __syncthreads();
    int base = 0;
    for (int w = 0; w < wid; w++) base += wsum[w];
    int incl = base + x;
    if (tid < NB_SCAN) g_bsum[tid] = incl - v;   // exclusive block prefix
    if (tid == NB_SCAN - 1) g_off[N_NODES] = incl;  // == N_EDGES
}

// Phase C: add block prefixes, materialize g_off/g_cursor.
__global__ __launch_bounds__(1024) void scanC_kernel() {
    int b = blockIdx.x, i = b * 1024 + threadIdx.x;
    if (i < N_NODES) {
        int off = g_off[i] + g_bsum[b];
        g_off[i] = off;
        g_cursor[i] = off;
    }
}

// bucket scatter of edge ids + weight packing folded in trailing blocks
#define NB_BUCKET ((N_EDGES + 511) / 512)
__global__ __launch_bounds__(512) void bucket_pack_kernel(
    const int* __restrict__ ei,
    const float* __restrict__ W0, const float* __restrict__ W1,
    const float* __restrict__ W2) {
    if (blockIdx.x < NB_BUCKET) {
        bool is64 = detect_i64(ei);
        int e = blockIdx.x * 512 + threadIdx.x;
        if (e >= N_EDGES) return;
        int d = dest_of(ei, e, is64);
        int pos = atomicAdd(&g_cursor[d], 1);
        g_eid[pos] = e;
        return;
    }
    int t = (blockIdx.x - NB_BUCKET) * 512 + threadIdx.x;
    if (t >= 10240) return;
    const float* W; uint2 *ph, *pl; int NT, Ncols, idx;
    if (t < 4096)       { W = W0; ph = g_W0h; pl = g_W0l; NT = 16; Ncols = 128; idx = t; }
    else if (t < 8192)  { W = W1; ph = g_W1h; pl = g_W1l; NT = 16; Ncols = 128; idx = t - 4096; }
    else                { W = W2; ph = g_W2h; pl = g_W2l; NT = 8;  Ncols = 64;  idx = t - 8192; }
    int lane = idx & 31, tile = idx >> 5;
    int nt = tile % NT, kt = tile / NT;
    int k0 = kt * 16 + (lane & 3) * 2;
    int n  = nt * 8  + (lane >> 2);
    float w00 = W[(k0    ) * Ncols + n];
    float w01 = W[(k0 + 1) * Ncols + n];
    float w10 = W[(k0 + 8) * Ncols + n];
    float w11 = W[(k0 + 9) * Ncols + n];
    ph[idx] = make_uint2(f2_to_h2(w00, w01), f2_to_h2(w10, w11));
    pl[idx] = make_uint2(f2_to_h2(h_res(w00), h_res(w01)), f2_to_h2(h_res(w10), h_res(w11)));
}

// ---------------- gather: one warp per node, 2 edges per LDG.128 ----------------
__global__ __launch_bounds__(256) void gather_kernel(const float4* __restrict__ ea4) {
    int w = (blockIdx.x * blockDim.x + threadIdx.x) >> 5;
    int lane = threadIdx.x & 31;
    if (w >= N_NODES) return;
    int half = lane >> 4, li = lane & 15;
    int i    = __ldg(&g_off[w]);
    int endo = __ldg(&g_off[w + 1]);
    float4 s = make_float4(0.f, 0.f, 0.f, 0.f);
    for (; i + 8 <= endo; i += 8) {
        int e0 = __ldg(&g_eid[i     + half]);
        int e1 = __ldg(&g_eid[i + 2 + half]);
        int e2 = __ldg(&g_eid[i + 4 + half]);
        int e3 = __ldg(&g_eid[i + 6 + half]);
        float4 v0 = __ldg(&ea4[(size_t)e0 * 16 + li]);
        float4 v1 = __ldg(&ea4[(size_t)e1 * 16 + li]);
        float4 v2 = __ldg(&ea4[(size_t)e2 * 16 + li]);
        float4 v3 = __ldg(&ea4[(size_t)e3 * 16 + li]);
        s.x += (v0.x + v1.x) + (v2.x + v3.x);
        s.y += (v0.y + v1.y) + (v2.y + v3.y);
        s.z += (v0.z + v1.z) + (v2.z + v3.z);
        s.w += (v0.w + v1.w) + (v2.w + v3.w);
    }
    for (; i + 2 <= endo; i += 2) {
        int e = __ldg(&g_eid[i + half]);
        float4 v = __ldg(&ea4[(size_t)e * 16 + li]);
        s.x += v.x; s.y += v.y; s.z += v.z; s.w += v.w;
    }
    if (i < endo && half == 0) {
        int e = __ldg(&g_eid[i]);
        float4 v = __ldg(&ea4[(size_t)e * 16 + li]);
        s.x += v.x; s.y += v.y; s.z += v.z; s.w += v.w;
    }
    s.x += __shfl_xor_sync(0xffffffffu, s.x, 16);
    s.y += __shfl_xor_sync(0xffffffffu, s.y, 16);
    s.z += __shfl_xor_sync(0xffffffffu, s.z, 16);
    s.w += __shfl_xor_sync(0xffffffffu, s.w, 16);
    if (half == 0)
        ((float4*)g_agg)[(size_t)w * 16 + li] = s;
}

// ---------------- fused MLP + LayerNorm + residual ----------------
// Per kt: batch ALL B-fragment LDGs first (MLP=16+), then ldmatrix.x4 A frags.
template <int NTW, int NTT>
__device__ __forceinline__ void gemm_layer(const __half* sh_hi, const __half* sh_lo,
                                           const uint2* __restrict__ Bh,
                                           const uint2* __restrict__ Bl,
                                           int warp_m, int ntile0, int lane,
                                           float acc[2][NTW][4]) {
#pragma unroll
    for (int mt = 0; mt < 2; mt++)
#pragma unroll
        for (int nt = 0; nt < NTW; nt++)
#pragma unroll
            for (int q = 0; q < 4; q++) acc[mt][nt][q] = 0.f;

    int lr = lane & 15;              // ldmatrix row within 16
    int lc = (lane >> 4) * 8;        // ldmatrix col half
#pragma unroll
    for (int kt = 0; kt < 8; kt++) {
        uint2 bh[NTW], bl[NTW];
#pragma unroll
        for (int nt = 0; nt < NTW; nt++) {
            int bi = (kt * NTT + ntile0 + nt) * 32 + lane;
            bh[nt] = __ldg(&Bh[bi]);
            bl[nt] = __ldg(&Bl[bi]);
        }
        uint32_t Ah[2][4], Al[2][4];
#pragma unroll
        for (int mt = 0; mt < 2; mt++) {
            const __half* base = sh_hi + (warp_m + mt * 16 + lr) * SW + kt * 16 + lc;
            ldsm_x4(Ah[mt], base);
            const __half* basel = sh_lo + (warp_m + mt * 16 + lr) * SW + kt * 16 + lc;
            ldsm_x4(Al[mt], basel);
        }
#pragma unroll
        for (int nt = 0; nt < NTW; nt++)
#pragma unroll
            for (int mt = 0; mt < 2; mt++) {
                mma16816(acc[mt][nt], Ah[mt], bh[nt]);   // hi * hi
                mma16816(acc[mt][nt], Al[mt], bh[nt]);   // lo * hi
                mma16816(acc[mt][nt], Ah[mt], bl[nt]);   // hi * lo
            }
    }
}

template <int NTW>
__device__ __forceinline__ void epilogue_relu(float acc[2][NTW][4],
                                              const float* __restrict__ bias,
                                              int warp_m, int ntile0, int lane,
                                              __half* sh_hi, __half* sh_lo) {
    __syncthreads();  // all warps done reading previous h
#pragma unroll
    for (int mt = 0; mt < 2; mt++)
#pragma unroll
        for (int nt = 0; nt < NTW; nt++) {
            int r0 = warp_m + mt * 16 + (lane >> 2);
            int c  = (ntile0 + nt) * 8 + (lane & 3) * 2;
            float bx = __ldg(&bias[c]), by = __ldg(&bias[c + 1]);
            float v0 = fmaxf(acc[mt][nt][0] + bx, 0.f);
            float v1 = fmaxf(acc[mt][nt][1] + by, 0.f);
            float v2 = fmaxf(acc[mt][nt][2] + bx, 0.f);
            float v3 = fmaxf(acc[mt][nt][3] + by, 0.f);
            *(uint32_t*)(sh_hi + r0 * SW + c)       = f2_to_h2(v0, v1);
            *(uint32_t*)(sh_lo + r0 * SW + c)       = f2_to_h2(h_res(v0), h_res(v1));
            *(uint32_t*)(sh_hi + (r0 + 8) * SW + c) = f2_to_h2(v2, v3);
            *(uint32_t*)(sh_lo + (r0 + 8) * SW + c) = f2_to_h2(h_res(v2), h_res(v3));
        }
    __syncthreads();
}

__global__ __launch_bounds__(256, 2) void mlp_kernel(
    const float* __restrict__ x,
    const float* __restrict__ b0, const float* __restrict__ b1,
    const float* __restrict__ b2,
    const float* __restrict__ lng, const float* __restrict__ lnb,
    float* __restrict__ out) {
    extern __shared__ __align__(16) unsigned char smem_raw[];
    __half* sh_hi = (__half*)smem_raw;
    __half* sh_lo = sh_hi + 128 * SW;
    float*  s_stat = (float*)(sh_lo + 128 * SW);  // mu[128], rstd[128]

    int tid = threadIdx.x, lane = tid & 31, w = tid >> 5;
    int block0 = blockIdx.x * TILE_M;

    // stage h0 = [x | agg] as fp16 hi/lo (float4 loads)
    const float4* x4   = (const float4*)x;
    const float4* agg4 = (const float4*)g_agg;
    for (int i = tid; i < 128 * 32; i += 256) {
        int r = i >> 5, c4 = i & 31;
        int nm = block0 + r;
        float4 v = make_float4(0.f, 0.f, 0.f, 0.f);
        if (nm < N_NODES)
            v = (c4 < 16) ? __ldg(&x4[(size_t)nm * 16 + c4])
                          : __ldg(&agg4[(size_t)nm * 16 + (c4 - 16)]);
        int c = c4 * 4;
        *(uint32_t*)(sh_hi + r * SW + c)     = f2_to_h2(v.x, v.y);
        *(uint32_t*)(sh_hi + r * SW + c + 2) = f2_to_h2(v.z, v.w);
        *(uint32_t*)(sh_lo + r * SW + c)     = f2_to_h2(h_res(v.x), h_res(v.y));
        *(uint32_t*)(sh_lo + r * SW + c + 2) = f2_to_h2(h_res(v.z), h_res(v.w));
    }
    __syncthreads();

    int warp_m = (w & 3) * 32;
    int wn = w >> 2;  // 0..1

    {
        float acc[2][8][4];
        gemm_layer<8, 16>(sh_hi, sh_lo, g_W0h, g_W0l, warp_m, wn * 8, lane, acc);
        epilogue_relu<8>(acc, b0, warp_m, wn * 8, lane, sh_hi, sh_lo);
        gemm_layer<8, 16>(sh_hi, sh_lo, g_W1h, g_W1l, warp_m, wn * 8, lane, acc);
        epilogue_relu<8>(acc, b1, warp_m, wn * 8, lane, sh_hi, sh_lo);
    }

    // layer 2: N = 64
    float* sy = (float*)smem_raw;  // 128 x 65 fp32 overlays sh_hi (written post-sync)
    {
        float acc2[2][4][4];
        gemm_layer<4, 8>(sh_hi, sh_lo, g_W2h, g_W2l, warp_m, wn * 4, lane, acc2);
        __syncthreads();  // everyone done reading h1 before overlay write
#pragma unroll
        for (int mt = 0; mt < 2; mt++)
#pragma unroll
            for (int nt = 0; nt < 4; nt++) {
                int r0 = warp_m + mt * 16 + (lane >> 2);
                int c  = (wn * 4 + nt) * 8 + (lane & 3) * 2;
                float bx = __ldg(&b2[c]), by = __ldg(&b2[c + 1]);
                sy[r0 * 65 + c]           = acc2[mt][nt][0] + bx;
                sy[r0 * 65 + c + 1]       = acc2[mt][nt][1] + by;
                sy[(r0 + 8) * 65 + c]     = acc2[mt][nt][2] + bx;
                sy[(r0 + 8) * 65 + c + 1] = acc2[mt][nt][3] + by;
            }
    }
    __syncthreads();

    // per-row LayerNorm stats
    if (tid < 128) {
        const float* row = sy + tid * 65;
        float s = 0.f, ss = 0.f;
#pragma unroll
        for (int c = 0; c < 64; c++) { float v = row[c]; s += v; ss += v * v; }
        float mu = s * 0.015625f;
        float var = ss * 0.015625f - mu * mu;
        s_stat[tid]       = mu;
        s_stat[128 + tid] = rsqrtf(var + 1e-5f);
    }
    __syncthreads();

    // coalesced normalize + residual + store
    for (int i = tid; i < 128 * 64; i += 256) {
        int r = i >> 6, c = i & 63;
        int nm = block0 + r;
        if (nm < N_NODES) {
            float v = sy[r * 65 + c];
            float res = (v - s_stat[r]) * s_stat[128 + r] * __ldg(&lng[c]) +
                        __ldg(&lnb[c]) + __ldg(&x[nm * 64 + c]);
            out[nm * 64 + c] = res;
        }
    }
}

// ---------------- launch ----------------
extern "C" void kernel_launch(void* const* d_in, const int* in_sizes, int n_in,
                              void* d_out, int out_size) {
    const float* x  = (const float*)d_in[0];
    const int*   ei = (const int*)d_in[1];   // int32 or int64; detected on device
    const float* ea = (const float*)d_in[2];
    const float* W0 = (const float*)d_in[3];
    const float* b0 = (const float*)d_in[4];
    const float* W1 = (const float*)d_in[5];
    const float* b1 = (const float*)d_in[6];
    const float* W2 = (const float*)d_in[7];
    const float* b2 = (const float*)d_in[8];
    const float* lg = (const float*)d_in[9];
    const float* lb = (const float*)d_in[10];
    float* out = (float*)d_out;

    // CSR build: histogram -> 3-phase parallel scan -> bucket scatter (+pack)
    hist_kernel<<<(N_EDGES + 511) / 512, 512>>>(ei);
    scanA_kernel<<<NB_SCAN, 1024>>>();
    scanB_kernel<<<1, 128>>>();
    scanC_kernel<<<NB_SCAN, 1024>>>();
    bucket_pack_kernel<<<NB_BUCKET + 20, 512>>>(ei, W0, W1, W2);

    // gather: one warp per node, 2 edges per LDG.128
    gather_kernel<<<(N_NODES * 32 + 255) / 256, 256>>>((const float4*)ea);

    // fused MLP + LN + residual
    const int smem_bytes = 2 * 128 * SW * (int)sizeof(__half) + 256 * (int)sizeof(float);
    cudaFuncSetAttribute(mlp_kernel, cudaFuncAttributeMaxDynamicSharedMemorySize, smem_bytes);
    int grid = (N_NODES + TILE_M - 1) / TILE_M;
    mlp_kernel<<<grid, 256, smem_bytes>>>(x, b0, b1, b2, lg, lb, out);
}

// round 8
// speedup vs baseline: 4.0537x; 1.1034x over previous
#include <cuda_runtime.h>
#include <cuda_fp16.h>
#include <cstdint>

#define N_NODES 100000
#define N_EDGES 1200000
#define D_NODE 64
#define HID 128
#define SW 136            // smem row stride in halfs (pad -> conflict-free mma/ldsm)
#define TILE_M 128

// ---------------- device scratch (no allocs allowed) ----------------
__device__ float g_agg[(size_t)N_NODES * 64];   // 25.6 MB, fully written by gather
__device__ int g_count[N_NODES];                // zero-init at load; scanAB re-zeroes after use
__device__ int g_off[N_NODES + 1];              // local (per-1024-block) exclusive offsets; [N]=last block total
__device__ int g_cursor[N_NODES];               // local fill cursors
__device__ int g_eid[N_EDGES];                  // edge ids sorted by destination
__device__ int g_bsumA[128];                    // raw per-block totals
__device__ int g_bsum[128];                     // exclusive block prefixes
__device__ int g_ticket;                        // decoupled-scan arrival counter (reset each replay)
// packed fp16 weight fragments (hi only): [kt][ntile][lane] -> uint2 (b0,b1 of m16n8k16 B frag)
__device__ uint2 g_W0h[8 * 16 * 32];
__device__ uint2 g_W1h[8 * 16 * 32];
__device__ uint2 g_W2h[8 *  8 * 32];

// ---------------- helpers ----------------
__device__ __forceinline__ uint32_t f2_to_h2(float a, float b) {
    __half ha = __float2half_rn(a), hb = __float2half_rn(b);
    return (uint32_t)__half_as_ushort(ha) | ((uint32_t)__half_as_ushort(hb) << 16);
}
__device__ __forceinline__ float h_res(float a) {
    return a - __half2float(__float2half_rn(a));
}
__device__ __forceinline__ bool detect_i64(const int* ei) {
    return (ei[1] == 0) & (ei[3] == 0) & (ei[5] == 0) & (ei[7] == 0);
}
__device__ __forceinline__ int dest_of(const int* ei, int e, bool is64) {
    if (is64) return (int)((const long long*)ei)[N_EDGES + e];
    return ei[N_EDGES + e];
}

__device__ __forceinline__ void mma16816(float c[4], const uint32_t a[4], uint2 b) {
    asm volatile(
        "mma.sync.aligned.m16n8k16.row.col.f32.f16.f16.f32 "
        "{%0,%1,%2,%3},{%4,%5,%6,%7},{%8,%9},{%0,%1,%2,%3};"
        : "+f"(c[0]), "+f"(c[1]), "+f"(c[2]), "+f"(c[3])
        : "r"(a[0]), "r"(a[1]), "r"(a[2]), "r"(a[3]), "r"(b.x), "r"(b.y));
}

__device__ __forceinline__ void ldsm_x4(uint32_t a[4], const __half* p) {
    uint32_t addr = (uint32_t)__cvta_generic_to_shared(p);
    asm volatile("ldmatrix.sync.aligned.m8n8.x4.shared.b16 {%0,%1,%2,%3}, [%4];"
                 : "=r"(a[0]), "=r"(a[1]), "=r"(a[2]), "=r"(a[3]) : "r"(addr));
}

// ---------------- CSR build ----------------
__global__ void hist_kernel(const int* __restrict__ ei) {
    bool is64 = detect_i64(ei);
    int e = blockIdx.x * blockDim.x + threadIdx.x;
    if (e >= N_EDGES) return;
    atomicAdd(&g_count[dest_of(ei, e, is64)], 1);
}

#define NB_SCAN ((N_NODES + 1023) / 1024)   // 98

// Single-pass scan: per-block local exclusive scan; the LAST block to arrive
// (atomic ticket) scans the 98 block totals into exclusive prefixes.
__global__ __launch_bounds__(1024) void scanAB_kernel() {
    __shared__ int s_tot[32], s_wx[32];
    __shared__ int s_last;
    int b = blockIdx.x, tid = threadIdx.x, lane = tid & 31, wid = tid >> 5;
    int i = b * 1024 + tid;
    int c = (i < N_NODES) ? g_count[i] : 0;
    if (i < N_NODES) g_count[i] = 0;         // reset for next replay
    int x = c;
#pragma unroll
    for (int d = 1; d < 32; d <<= 1) {
        int y = __shfl_up_sync(0xffffffffu, x, d);
        if (lane >= d) x += y;
    }
    if (lane == 31) s_tot[wid] = x;
    __syncthreads();
    if (wid == 0) {
        int v = s_tot[lane];
        int inc = v;
#pragma unroll
        for (int d = 1; d < 32; d <<= 1) {
            int y = __shfl_up_sync(0xffffffffu, inc, d);
            if (lane >= d) inc += y;
        }
        s_wx[lane] = inc - v;
        if (lane == 31) g_bsumA[b] = inc;    // raw block total
    }
    __syncthreads();
    if (i < N_NODES) {
        int loc = s_wx[wid] + (x - c);       // local exclusive offset
        g_off[i] = loc;
        g_cursor[i] = loc;
    }
    // ---- decoupled phase B: last-arriving block scans block totals ----
    __threadfence();
    if (tid == 0) {
        int t = atomicAdd(&g_ticket, 1);
        s_last = (t == NB_SCAN - 1) ? 1 : 0;
    }
    __syncthreads();
    if (s_last) {
        if (tid == 0) g_ticket = 0;          // reset for next replay
        int v = (tid < NB_SCAN) ? g_bsumA[tid] : 0;
        int y = v;
#pragma unroll
        for (int d = 1; d < 32; d <<= 1) {
            int z = __shfl_up_sync(0xffffffffu, y, d);
            if (lane >= d) y += z;
        }
        if (lane == 31) s_tot[wid] = y;
        __syncthreads();
        int base = 0;
        for (int w = 0; w < wid; w++) base += s_tot[w];
        if (tid < NB_SCAN) {
            g_bsum[tid] = base + y - v;      // exclusive block prefix
            if (tid == NB_SCAN - 1)
                g_off[N_NODES] = v;          // so g_off[N]+g_bsum[97] == N_EDGES
        }
    }
}

// bucket scatter of edge ids (+ weight packing folded in trailing blocks)
#define NB_BUCKET ((N_EDGES + 511) / 512)
__global__ __launch_bounds__(512) void bucket_pack_kernel(
    const int* __restrict__ ei,
    const float* __restrict__ W0, const float* __restrict__ W1,
    const float* __restrict__ W2) {
    if (blockIdx.x < NB_BUCKET) {
        bool is64 = detect_i64(ei);
        int e = blockIdx.x * 512 + threadIdx.x;
        if (e >= N_EDGES) return;
        int d = dest_of(ei, e, is64);
        int pos = atomicAdd(&g_cursor[d], 1) + __ldg(&g_bsum[d >> 10]);
        g_eid[pos] = e;
        return;
    }
    // ---- pack: fp32 weights -> hi fp16 mma B fragments ----
    int t = (blockIdx.x - NB_BUCKET) * 512 + threadIdx.x;
    if (t >= 10240) return;
    const float* W; uint2 *ph; int NT, Ncols, idx;
    if (t < 4096)       { W = W0; ph = g_W0h; NT = 16; Ncols = 128; idx = t; }
    else if (t < 8192)  { W = W1; ph = g_W1h; NT = 16; Ncols = 128; idx = t - 4096; }
    else                { W = W2; ph = g_W2h; NT = 8;  Ncols = 64;  idx = t - 8192; }
    int lane = idx & 31, tile = idx >> 5;
    int nt = tile % NT, kt = tile / NT;
    int k0 = kt * 16 + (lane & 3) * 2;
    int n  = nt * 8  + (lane >> 2);
    float w00 = W[(k0    ) * Ncols + n];
    float w01 = W[(k0 + 1) * Ncols + n];
    float w10 = W[(k0 + 8) * Ncols + n];
    float w11 = W[(k0 + 9) * Ncols + n];
    ph[idx] = make_uint2(f2_to_h2(w00, w01), f2_to_h2(w10, w11));
}

// ---------------- gather: one warp per node, 2 edges per LDG.128 ----------------
__global__ __launch_bounds__(256) void gather_kernel(const float4* __restrict__ ea4) {
    int w = (blockIdx.x * blockDim.x + threadIdx.x) >> 5;
    int lane = threadIdx.x & 31;
    if (w >= N_NODES) return;
    int half = lane >> 4, li = lane & 15;
    int i    = __ldg(&g_off[w])     + __ldg(&g_bsum[w >> 10]);
    int endo = __ldg(&g_off[w + 1]) + __ldg(&g_bsum[(w + 1) >> 10]);
    float4 s = make_float4(0.f, 0.f, 0.f, 0.f);
    for (; i + 8 <= endo; i += 8) {
        int e0 = __ldg(&g_eid[i     + half]);
        int e1 = __ldg(&g_eid[i + 2 + half]);
        int e2 = __ldg(&g_eid[i + 4 + half]);
        int e3 = __ldg(&g_eid[i + 6 + half]);
        float4 v0 = __ldg(&ea4[(size_t)e0 * 16 + li]);
        float4 v1 = __ldg(&ea4[(size_t)e1 * 16 + li]);
        float4 v2 = __ldg(&ea4[(size_t)e2 * 16 + li]);
        float4 v3 = __ldg(&ea4[(size_t)e3 * 16 + li]);
        s.x += (v0.x + v1.x) + (v2.x + v3.x);
        s.y += (v0.y + v1.y) + (v2.y + v3.y);
        s.z += (v0.z + v1.z) + (v2.z + v3.z);
        s.w += (v0.w + v1.w) + (v2.w + v3.w);
    }
    for (; i + 2 <= endo; i += 2) {
        int e = __ldg(&g_eid[i + half]);
        float4 v = __ldg(&ea4[(size_t)e * 16 + li]);
        s.x += v.x; s.y += v.y; s.z += v.z; s.w += v.w;
    }
    if (i < endo && half == 0) {
        int e = __ldg(&g_eid[i]);
        float4 v = __ldg(&ea4[(size_t)e * 16 + li]);
        s.x += v.x; s.y += v.y; s.z += v.z; s.w += v.w;
    }
    s.x += __shfl_xor_sync(0xffffffffu, s.x, 16);
    s.y += __shfl_xor_sync(0xffffffffu, s.y, 16);
    s.z += __shfl_xor_sync(0xffffffffu, s.z, 16);
    s.w += __shfl_xor_sync(0xffffffffu, s.w, 16);
    if (half == 0)
        ((float4*)g_agg)[(size_t)w * 16 + li] = s;
}

// ---------------- fused MLP + LayerNorm + residual ----------------
// 2-term split: acc += Ah*Bh + Al*Bh (input hi/lo, weights fp16-hi only).
template <int NTW, int NTT>
__device__ __forceinline__ void gemm_layer(const __half* sh_hi, const __half* sh_lo,
                                           const uint2* __restrict__ Bh,
                                           int warp_m, int ntile0, int lane,
                                           float acc[2][NTW][4]) {
#pragma unroll
    for (int mt = 0; mt < 2; mt++)
#pragma unroll
        for (int nt = 0; nt < NTW; nt++)
#pragma unroll
            for (int q = 0; q < 4; q++) acc[mt][nt][q] = 0.f;

    int lr = lane & 15;              // ldmatrix row within 16
    int lc = (lane >> 4) * 8;        // ldmatrix col half
#pragma unroll
    for (int kt = 0; kt < 8; kt++) {
        uint2 bh[NTW];
#pragma unroll
        for (int nt = 0; nt < NTW; nt++) {
            int bi = (kt * NTT + ntile0 + nt) * 32 + lane;
            bh[nt] = __ldg(&Bh[bi]);
        }
        uint32_t Ah[2][4], Al[2][4];
#pragma unroll
        for (int mt = 0; mt < 2; mt++) {
            ldsm_x4(Ah[mt], sh_hi + (warp_m + mt * 16 + lr) * SW + kt * 16 + lc);
            ldsm_x4(Al[mt], sh_lo + (warp_m + mt * 16 + lr) * SW + kt * 16 + lc);
        }
#pragma unroll
        for (int nt = 0; nt < NTW; nt++)
#pragma unroll
            for (int mt = 0; mt < 2; mt++) {
                mma16816(acc[mt][nt], Ah[mt], bh[nt]);   // hi * W
                mma16816(acc[mt][nt], Al[mt], bh[nt]);   // lo * W
            }
    }
}

template <int NTW>
__device__ __forceinline__ void epilogue_relu(float acc[2][NTW][4],
                                              const float* __restrict__ bias,
                                              int warp_m, int ntile0, int lane,
                                              __half* sh_hi, __half* sh_lo) {
    __syncthreads();  // all warps done reading previous h
#pragma unroll
    for (int mt = 0; mt < 2; mt++)
#pragma unroll
        for (int nt = 0; nt < NTW; nt++) {
            int r0 = warp_m + mt * 16 + (lane >> 2);
            int c  = (ntile0 + nt) * 8 + (lane & 3) * 2;
            float bx = __ldg(&bias[c]), by = __ldg(&bias[c + 1]);
            float v0 = fmaxf(acc[mt][nt][0] + bx, 0.f);
            float v1 = fmaxf(acc[mt][nt][1] + by, 0.f);
            float v2 = fmaxf(acc[mt][nt][2] + bx, 0.f);
            float v3 = fmaxf(acc[mt][nt][3] + by, 0.f);
            *(uint32_t*)(sh_hi + r0 * SW + c)       = f2_to_h2(v0, v1);
            *(uint32_t*)(sh_lo + r0 * SW + c)       = f2_to_h2(h_res(v0), h_res(v1));
            *(uint32_t*)(sh_hi + (r0 + 8) * SW + c) = f2_to_h2(v2, v3);
            *(uint32_t*)(sh_lo + (r0 + 8) * SW + c) = f2_to_h2(h_res(v2), h_res(v3));
        }
    __syncthreads();
}

__global__ __launch_bounds__(256, 2) void mlp_kernel(
    const float* __restrict__ x,
    const float* __restrict__ b0, const float* __restrict__ b1,
    const float* __restrict__ b2,
    const float* __restrict__ lng, const float* __restrict__ lnb,
    float* __restrict__ out) {
    extern __shared__ __align__(16) unsigned char smem_raw[];
    __half* sh_hi = (__half*)smem_raw;
    __half* sh_lo = sh_hi + 128 * SW;
    float*  s_stat = (float*)(sh_lo + 128 * SW);  // mu[128], rstd[128]

    int tid = threadIdx.x, lane = tid & 31, w = tid >> 5;
    int block0 = blockIdx.x * TILE_M;

    // stage h0 = [x | agg] as fp16 hi/lo (float4 loads)
    const float4* x4   = (const float4*)x;
    const float4* agg4 = (const float4*)g_agg;
    for (int i = tid; i < 128 * 32; i += 256) {
        int r = i >> 5, c4 = i & 31;
        int nm = block0 + r;
        float4 v = make_float4(0.f, 0.f, 0.f, 0.f);
        if (nm < N_NODES)
            v = (c4 < 16) ? __ldg(&x4[(size_t)nm * 16 + c4])
                          : __ldg(&agg4[(size_t)nm * 16 + (c4 - 16)]);
        int c = c4 * 4;
        *(uint32_t*)(sh_hi + r * SW + c)     = f2_to_h2(v.x, v.y);
        *(uint32_t*)(sh_hi + r * SW + c + 2) = f2_to_h2(v.z, v.w);
        *(uint32_t*)(sh_lo + r * SW + c)     = f2_to_h2(h_res(v.x), h_res(v.y));
        *(uint32_t*)(sh_lo + r * SW + c + 2) = f2_to_h2(h_res(v.z), h_res(v.w));
    }
    __syncthreads();

    int warp_m = (w & 3) * 32;
    int wn = w >> 2;  // 0..1

    {
        float acc[2][8][4];
        gemm_layer<8, 16>(sh_hi, sh_lo, g_W0h, warp_m, wn * 8, lane, acc);
        epilogue_relu<8>(acc, b0, warp_m, wn * 8, lane, sh_hi, sh_lo);
        gemm_layer<8, 16>(sh_hi, sh_lo, g_W1h, warp_m, wn * 8, lane, acc);
        epilogue_relu<8>(acc, b1, warp_m, wn * 8, lane, sh_hi, sh_lo);
    }

    // layer 2: N = 64
    float* sy = (float*)smem_raw;  // 128 x 65 fp32 overlays sh_hi (written post-sync)
    {
        float acc2[2][4][4];
        gemm_layer<4, 8>(sh_hi, sh_lo, g_W2h, warp_m, wn * 4, lane, acc2);
        __syncthreads();  // everyone done reading h1 before overlay write
#pragma unroll
        for (int mt = 0; mt < 2; mt++)
#pragma unroll
            for (int nt = 0; nt < 4; nt++) {
                int r0 = warp_m + mt * 16 + (lane >> 2);
                int c  = (wn * 4 + nt) * 8 + (lane & 3) * 2;
                float bx = __ldg(&b2[c]), by = __ldg(&b2[c + 1]);
                sy[r0 * 65 + c]           = acc2[mt][nt][0] + bx;
                sy[r0 * 65 + c + 1]       = acc2[mt][nt][1] + by;
                sy[(r0 + 8) * 65 + c]     = acc2[mt][nt][2] + bx;
                sy[(r0 + 8) * 65 + c + 1] = acc2[mt][nt][3] + by;
            }
    }
    __syncthreads();

    // per-row LayerNorm stats
    if (tid < 128) {
        const float* row = sy + tid * 65;
        float s = 0.f, ss = 0.f;
#pragma unroll
        for (int c = 0; c < 64; c++) { float v = row[c]; s += v; ss += v * v; }
        float mu = s * 0.015625f;
        float var = ss * 0.015625f - mu * mu;
        s_stat[tid]       = mu;
        s_stat[128 + tid] = rsqrtf(var + 1e-5f);
    }
    __syncthreads();

    // coalesced normalize + residual + store
    for (int i = tid; i < 128 * 64; i += 256) {
        int r = i >> 6, c = i & 63;
        int nm = block0 + r;
        if (nm < N_NODES) {
            float v = sy[r * 65 + c];
            float res = (v - s_stat[r]) * s_stat[128 + r] * __ldg(&lng[c]) +
                        __ldg(&lnb[c]) + __ldg(&x[nm * 64 + c]);
            out[nm * 64 + c] = res;
        }
    }
}

// ---------------- launch (5 kernels; gather at profiled index 3) ----------------
extern "C" void kernel_launch(void* const* d_in, const int* in_sizes, int n_in,
                              void* d_out, int out_size) {
    const float* x  = (const float*)d_in[0];
    const int*   ei = (const int*)d_in[1];   // int32 or int64; detected on device
    const float* ea = (const float*)d_in[2];
    const float* W0 = (const float*)d_in[3];
    const float* b0 = (const float*)d_in[4];
    const float* W1 = (const float*)d_in[5];
    const float* b1 = (const float*)d_in[6];
    const float* W2 = (const float*)d_in[7];
    const float* b2 = (const float*)d_in[8];
    const float* lg = (const float*)d_in[9];
    const float* lb = (const float*)d_in[10];
    float* out = (float*)d_out;

    hist_kernel<<<(N_EDGES + 511) / 512, 512>>>(ei);
    scanAB_kernel<<<NB_SCAN, 1024>>>();
    bucket_pack_kernel<<<NB_BUCKET + 20, 512>>>(ei, W0, W1, W2);
    gather_kernel<<<(N_NODES * 32 + 255) / 256, 256>>>((const float4*)ea);

    const int smem_bytes = 2 * 128 * SW * (int)sizeof(__half) + 256 * (int)sizeof(float);
    cudaFuncSetAttribute(mlp_kernel, cudaFuncAttributeMaxDynamicSharedMemorySize, smem_bytes);
    int grid = (N_NODES + TILE_M - 1) / TILE_M;
    mlp_kernel<<<grid, 256, smem_bytes>>>(x, b0, b1, b2, lg, lb, out);
}

// round 9
// speedup vs baseline: 4.3702x; 1.0781x over previous
#include <cuda_runtime.h>
#include <cuda_fp16.h>
#include <cstdint>

#define N_NODES 100000
#define N_EDGES 1200000
#define D_NODE 64
#define HID 128
#define SW 136            // smem row stride in halfs (pad -> conflict-free mma/ldsm)
#define TILE_M 64

// ---------------- device scratch (no allocs allowed) ----------------
__device__ float g_agg[(size_t)N_NODES * 64];   // 25.6 MB, fully written by gather
__device__ int g_count[N_NODES];                // zero-init at load; scanAB re-zeroes after use
__device__ int g_off[N_NODES + 1];              // local (per-1024-block) exclusive offsets; [N]=last block total
__device__ int g_cursor[N_NODES];               // local fill cursors
__device__ int g_eid[N_EDGES];                  // edge ids sorted by destination
__device__ int g_bsumA[128];                    // raw per-block totals
__device__ int g_bsum[128];                     // exclusive block prefixes
__device__ int g_ticket;                        // decoupled-scan arrival counter (reset each replay)
// packed fp16 weight fragments (hi only): [kt][ntile][lane] -> uint2 (b0,b1 of m16n8k16 B frag)
__device__ uint2 g_W0h[8 * 16 * 32];
__device__ uint2 g_W1h[8 * 16 * 32];
__device__ uint2 g_W2h[8 *  8 * 32];

// ---------------- helpers ----------------
__device__ __forceinline__ uint32_t f2_to_h2(float a, float b) {
    __half ha = __float2half_rn(a), hb = __float2half_rn(b);
    return (uint32_t)__half_as_ushort(ha) | ((uint32_t)__half_as_ushort(hb) << 16);
}
__device__ __forceinline__ float h_res(float a) {
    return a - __half2float(__float2half_rn(a));
}
__device__ __forceinline__ bool detect_i64(const int* ei) {
    return (ei[1] == 0) & (ei[3] == 0) & (ei[5] == 0) & (ei[7] == 0);
}
__device__ __forceinline__ int dest_of(const int* ei, int e, bool is64) {
    if (is64) return (int)((const long long*)ei)[N_EDGES + e];
    return ei[N_EDGES + e];
}

__device__ __forceinline__ void mma16816(float c[4], const uint32_t a[4], uint2 b) {
    asm volatile(
        "mma.sync.aligned.m16n8k16.row.col.f32.f16.f16.f32 "
        "{%0,%1,%2,%3},{%4,%5,%6,%7},{%8,%9},{%0,%1,%2,%3};"
        : "+f"(c[0]), "+f"(c[1]), "+f"(c[2]), "+f"(c[3])
        : "r"(a[0]), "r"(a[1]), "r"(a[2]), "r"(a[3]), "r"(b.x), "r"(b.y));
}

__device__ __forceinline__ void ldsm_x4(uint32_t a[4], const __half* p) {
    uint32_t addr = (uint32_t)__cvta_generic_to_shared(p);
    asm volatile("ldmatrix.sync.aligned.m8n8.x4.shared.b16 {%0,%1,%2,%3}, [%4];"
                 : "=r"(a[0]), "=r"(a[1]), "=r"(a[2]), "=r"(a[3]) : "r"(addr));
}

// ---------------- CSR build ----------------
__global__ void hist_kernel(const int* __restrict__ ei) {
    bool is64 = detect_i64(ei);
    int e = blockIdx.x * blockDim.x + threadIdx.x;
    if (e >= N_EDGES) return;
    atomicAdd(&g_count[dest_of(ei, e, is64)], 1);
}

#define NB_SCAN ((N_NODES + 1023) / 1024)   // 98

// Single-pass scan: per-block local exclusive scan; the LAST block to arrive
// (atomic ticket) scans the 98 block totals into exclusive prefixes.
__global__ __launch_bounds__(1024) void scanAB_kernel() {
    __shared__ int s_tot[32], s_wx[32];
    __shared__ int s_last;
    int b = blockIdx.x, tid = threadIdx.x, lane = tid & 31, wid = tid >> 5;
    int i = b * 1024 + tid;
    int c = (i < N_NODES) ? g_count[i] : 0;
    if (i < N_NODES) g_count[i] = 0;         // reset for next replay
    int x = c;
#pragma unroll
    for (int d = 1; d < 32; d <<= 1) {
        int y = __shfl_up_sync(0xffffffffu, x, d);
        if (lane >= d) x += y;
    }
    if (lane == 31) s_tot[wid] = x;
    __syncthreads();
    if (wid == 0) {
        int v = s_tot[lane];
        int inc = v;
#pragma unroll
        for (int d = 1; d < 32; d <<= 1) {
            int y = __shfl_up_sync(0xffffffffu, inc, d);
            if (lane >= d) inc += y;
        }
        s_wx[lane] = inc - v;
        if (lane == 31) g_bsumA[b] = inc;    // raw block total
    }
    __syncthreads();
    if (i < N_NODES) {
        int loc = s_wx[wid] + (x - c);       // local exclusive offset
        g_off[i] = loc;
        g_cursor[i] = loc;
    }
    // ---- decoupled phase B: last-arriving block scans block totals ----
    __threadfence();
    if (tid == 0) {
        int t = atomicAdd(&g_ticket, 1);
        s_last = (t == NB_SCAN - 1) ? 1 : 0;
    }
    __syncthreads();
    if (s_last) {
        if (tid == 0) g_ticket = 0;          // reset for next replay
        int v = (tid < NB_SCAN) ? g_bsumA[tid] : 0;
        int y = v;
#pragma unroll
        for (int d = 1; d < 32; d <<= 1) {
            int z = __shfl_up_sync(0xffffffffu, y, d);
            if (lane >= d) y += z;
        }
        if (lane == 31) s_tot[wid] = y;
        __syncthreads();
        int base = 0;
        for (int w = 0; w < wid; w++) base += s_tot[w];
        if (tid < NB_SCAN) {
            g_bsum[tid] = base + y - v;      // exclusive block prefix
            if (tid == NB_SCAN - 1)
                g_off[N_NODES] = v;          // so g_off[N]+g_bsum[97] == N_EDGES
        }
    }
}

// bucket scatter of edge ids (+ weight packing folded in trailing blocks)
#define NB_BUCKET ((N_EDGES + 511) / 512)
__global__ __launch_bounds__(512) void bucket_pack_kernel(
    const int* __restrict__ ei,
    const float* __restrict__ W0, const float* __restrict__ W1,
    const float* __restrict__ W2) {
    if (blockIdx.x < NB_BUCKET) {
        bool is64 = detect_i64(ei);
        int e = blockIdx.x * 512 + threadIdx.x;
        if (e >= N_EDGES) return;
        int d = dest_of(ei, e, is64);
        int pos = atomicAdd(&g_cursor[d], 1) + __ldg(&g_bsum[d >> 10]);
        g_eid[pos] = e;
        return;
    }
    // ---- pack: fp32 weights -> hi fp16 mma B fragments ----
    int t = (blockIdx.x - NB_BUCKET) * 512 + threadIdx.x;
    if (t >= 10240) return;
    const float* W; uint2 *ph; int NT, Ncols, idx;
    if (t < 4096)       { W = W0; ph = g_W0h; NT = 16; Ncols = 128; idx = t; }
    else if (t < 8192)  { W = W1; ph = g_W1h; NT = 16; Ncols = 128; idx = t - 4096; }
    else                { W = W2; ph = g_W2h; NT = 8;  Ncols = 64;  idx = t - 8192; }
    int lane = idx & 31, tile = idx >> 5;
    int nt = tile % NT, kt = tile / NT;
    int k0 = kt * 16 + (lane & 3) * 2;
    int n  = nt * 8  + (lane >> 2);
    float w00 = W[(k0    ) * Ncols + n];
    float w01 = W[(k0 + 1) * Ncols + n];
    float w10 = W[(k0 + 8) * Ncols + n];
    float w11 = W[(k0 + 9) * Ncols + n];
    ph[idx] = make_uint2(f2_to_h2(w00, w01), f2_to_h2(w10, w11));
}

// ---------------- gather: one warp per node, 2 edges per LDG.128 ----------------
__global__ __launch_bounds__(256) void gather_kernel(const float4* __restrict__ ea4) {
    int w = (blockIdx.x * blockDim.x + threadIdx.x) >> 5;
    int lane = threadIdx.x & 31;
    if (w >= N_NODES) return;
    int half = lane >> 4, li = lane & 15;
    int i    = __ldg(&g_off[w])     + __ldg(&g_bsum[w >> 10]);
    int endo = __ldg(&g_off[w + 1]) + __ldg(&g_bsum[(w + 1) >> 10]);
    float4 s = make_float4(0.f, 0.f, 0.f, 0.f);
    for (; i + 8 <= endo; i += 8) {
        int e0 = __ldg(&g_eid[i     + half]);
        int e1 = __ldg(&g_eid[i + 2 + half]);
        int e2 = __ldg(&g_eid[i + 4 + half]);
        int e3 = __ldg(&g_eid[i + 6 + half]);
        float4 v0 = __ldg(&ea4[(size_t)e0 * 16 + li]);
        float4 v1 = __ldg(&ea4[(size_t)e1 * 16 + li]);
        float4 v2 = __ldg(&ea4[(size_t)e2 * 16 + li]);
        float4 v3 = __ldg(&ea4[(size_t)e3 * 16 + li]);
        s.x += (v0.x + v1.x) + (v2.x + v3.x);
        s.y += (v0.y + v1.y) + (v2.y + v3.y);
        s.z += (v0.z + v1.z) + (v2.z + v3.z);
        s.w += (v0.w + v1.w) + (v2.w + v3.w);
    }
    for (; i + 2 <= endo; i += 2) {
        int e = __ldg(&g_eid[i + half]);
        float4 v = __ldg(&ea4[(size_t)e * 16 + li]);
        s.x += v.x; s.y += v.y; s.z += v.z; s.w += v.w;
    }
    if (i < endo && half == 0) {
        int e = __ldg(&g_eid[i]);
        float4 v = __ldg(&ea4[(size_t)e * 16 + li]);
        s.x += v.x; s.y += v.y; s.z += v.z; s.w += v.w;
    }
    s.x += __shfl_xor_sync(0xffffffffu, s.x, 16);
    s.y += __shfl_xor_sync(0xffffffffu, s.y, 16);
    s.z += __shfl_xor_sync(0xffffffffu, s.z, 16);
    s.w += __shfl_xor_sync(0xffffffffu, s.w, 16);
    if (half == 0)
        ((float4*)g_agg)[(size_t)w * 16 + li] = s;
}

// ---------------- fused MLP + LayerNorm + residual (TILE_M = 64, occ 3) ----------
// 2-term split: acc += Ah*Bh + Al*Bh (input hi/lo, weights fp16-hi only).
template <int NTW, int NTT>
__device__ __forceinline__ void gemm_layer(const __half* sh_hi, const __half* sh_lo,
                                           const uint2* __restrict__ Bh,
                                           int warp_m, int ntile0, int lane,
                                           float acc[2][NTW][4]) {
#pragma unroll
    for (int mt = 0; mt < 2; mt++)
#pragma unroll
        for (int nt = 0; nt < NTW; nt++)
#pragma unroll
            for (int q = 0; q < 4; q++) acc[mt][nt][q] = 0.f;

    int lr = lane & 15;              // ldmatrix row within 16
    int lc = (lane >> 4) * 8;        // ldmatrix col half
#pragma unroll
    for (int kt = 0; kt < 8; kt++) {
        uint2 bh[NTW];
#pragma unroll
        for (int nt = 0; nt < NTW; nt++) {
            int bi = (kt * NTT + ntile0 + nt) * 32 + lane;
            bh[nt] = __ldg(&Bh[bi]);
        }
        uint32_t Ah[2][4], Al[2][4];
#pragma unroll
        for (int mt = 0; mt < 2; mt++) {
            ldsm_x4(Ah[mt], sh_hi + (warp_m + mt * 16 + lr) * SW + kt * 16 + lc);
            ldsm_x4(Al[mt], sh_lo + (warp_m + mt * 16 + lr) * SW + kt * 16 + lc);
        }
#pragma unroll
        for (int nt = 0; nt < NTW; nt++)
#pragma unroll
            for (int mt = 0; mt < 2; mt++) {
                mma16816(acc[mt][nt], Ah[mt], bh[nt]);   // hi * W
                mma16816(acc[mt][nt], Al[mt], bh[nt]);   // lo * W
            }
    }
}

template <int NTW>
__device__ __forceinline__ void epilogue_relu(float acc[2][NTW][4],
                                              const float* __restrict__ bias,
                                              int warp_m, int ntile0, int lane,
                                              __half* sh_hi, __half* sh_lo) {
    __syncthreads();  // all warps done reading previous h
#pragma unroll
    for (int mt = 0; mt < 2; mt++)
#pragma unroll
        for (int nt = 0; nt < NTW; nt++) {
            int r0 = warp_m + mt * 16 + (lane >> 2);
            int c  = (ntile0 + nt) * 8 + (lane & 3) * 2;
            float bx = __ldg(&bias[c]), by = __ldg(&bias[c + 1]);
            float v0 = fmaxf(acc[mt][nt][0] + bx, 0.f);
            float v1 = fmaxf(acc[mt][nt][1] + by, 0.f);
            float v2 = fmaxf(acc[mt][nt][2] + bx, 0.f);
            float v3 = fmaxf(acc[mt][nt][3] + by, 0.f);
            *(uint32_t*)(sh_hi + r0 * SW + c)       = f2_to_h2(v0, v1);
            *(uint32_t*)(sh_lo + r0 * SW + c)       = f2_to_h2(h_res(v0), h_res(v1));
            *(uint32_t*)(sh_hi + (r0 + 8) * SW + c) = f2_to_h2(v2, v3);
            *(uint32_t*)(sh_lo + (r0 + 8) * SW + c) = f2_to_h2(h_res(v2), h_res(v3));
        }
    __syncthreads();
}

__global__ __launch_bounds__(256, 3) void mlp_kernel(
    const float* __restrict__ x,
    const float* __restrict__ b0, const float* __restrict__ b1,
    const float* __restrict__ b2,
    const float* __restrict__ lng, const float* __restrict__ lnb,
    float* __restrict__ out) {
    extern __shared__ __align__(16) unsigned char smem_raw[];
    __half* sh_hi = (__half*)smem_raw;                    // 64 x SW halfs
    __half* sh_lo = sh_hi + TILE_M * SW;
    float*  s_stat = (float*)(sh_lo + TILE_M * SW);       // mu[64], rstd[64]

    int tid = threadIdx.x, lane = tid & 31, w = tid >> 5;
    int block0 = blockIdx.x * TILE_M;

    // stage h0 = [x | agg] as fp16 hi/lo (float4 loads): 64 rows x 32 float4
    const float4* x4   = (const float4*)x;
    const float4* agg4 = (const float4*)g_agg;
    for (int i = tid; i < TILE_M * 32; i += 256) {
        int r = i >> 5, c4 = i & 31;
        int nm = block0 + r;
        float4 v = make_float4(0.f, 0.f, 0.f, 0.f);
        if (nm < N_NODES)
            v = (c4 < 16) ? __ldg(&x4[(size_t)nm * 16 + c4])
                          : __ldg(&agg4[(size_t)nm * 16 + (c4 - 16)]);
        int c = c4 * 4;
        *(uint32_t*)(sh_hi + r * SW + c)     = f2_to_h2(v.x, v.y);
        *(uint32_t*)(sh_hi + r * SW + c + 2) = f2_to_h2(v.z, v.w);
        *(uint32_t*)(sh_lo + r * SW + c)     = f2_to_h2(h_res(v.x), h_res(v.y));
        *(uint32_t*)(sh_lo + r * SW + c + 2) = f2_to_h2(h_res(v.z), h_res(v.w));
    }
    __syncthreads();

    int warp_m = (w & 1) * 32;    // 2 M-groups of 32 rows
    int wn = w >> 1;              // 0..3 N-groups

    {
        float acc[2][4][4];
        gemm_layer<4, 16>(sh_hi, sh_lo, g_W0h, warp_m, wn * 4, lane, acc);
        epilogue_relu<4>(acc, b0, warp_m, wn * 4, lane, sh_hi, sh_lo);
        gemm_layer<4, 16>(sh_hi, sh_lo, g_W1h, warp_m, wn * 4, lane, acc);
        epilogue_relu<4>(acc, b1, warp_m, wn * 4, lane, sh_hi, sh_lo);
    }

    // layer 2: N = 64
    float* sy = (float*)smem_raw;  // 64 x 65 fp32 overlays sh_hi (written post-sync)
    {
        float acc2[2][2][4];
        gemm_layer<2, 8>(sh_hi, sh_lo, g_W2h, warp_m, wn * 2, lane, acc2);
        __syncthreads();  // everyone done reading h1 before overlay write
#pragma unroll
        for (int mt = 0; mt < 2; mt++)
#pragma unroll
            for (int nt = 0; nt < 2; nt++) {
                int r0 = warp_m + mt * 16 + (lane >> 2);
                int c  = (wn * 2 + nt) * 8 + (lane & 3) * 2;
                float bx = __ldg(&b2[c]), by = __ldg(&b2[c + 1]);
                sy[r0 * 65 + c]           = acc2[mt][nt][0] + bx;
                sy[r0 * 65 + c + 1]       = acc2[mt][nt][1] + by;
                sy[(r0 + 8) * 65 + c]     = acc2[mt][nt][2] + bx;
                sy[(r0 + 8) * 65 + c + 1] = acc2[mt][nt][3] + by;
            }
    }
    __syncthreads();

    // per-row LayerNorm stats
    if (tid < TILE_M) {
        const float* row = sy + tid * 65;
        float s = 0.f, ss = 0.f;
#pragma unroll
        for (int c = 0; c < 64; c++) { float v = row[c]; s += v; ss += v * v; }
        float mu = s * 0.015625f;
        float var = ss * 0.015625f - mu * mu;
        s_stat[tid]          = mu;
        s_stat[TILE_M + tid] = rsqrtf(var + 1e-5f);
    }
    __syncthreads();

    // coalesced normalize + residual + store
    for (int i = tid; i < TILE_M * 64; i += 256) {
        int r = i >> 6, c = i & 63;
        int nm = block0 + r;
        if (nm < N_NODES) {
            float v = sy[r * 65 + c];
            float res = (v - s_stat[r]) * s_stat[TILE_M + r] * __ldg(&lng[c]) +
                        __ldg(&lnb[c]) + __ldg(&x[nm * 64 + c]);
            out[nm * 64 + c] = res;
        }
    }
}

// ---------------- launch (5 kernels; gather at profiled index 3) ----------------
extern "C" void kernel_launch(void* const* d_in, const int* in_sizes, int n_in,
                              void* d_out, int out_size) {
    const float* x  = (const float*)d_in[0];
    const int*   ei = (const int*)d_in[1];   // int32 or int64; detected on device
    const float* ea = (const float*)d_in[2];
    const float* W0 = (const float*)d_in[3];
    const float* b0 = (const float*)d_in[4];
    const float* W1 = (const float*)d_in[5];
    const float* b1 = (const float*)d_in[6];
    const float* W2 = (const float*)d_in[7];
    const float* b2 = (const float*)d_in[8];
    const float* lg = (const float*)d_in[9];
    const float* lb = (const float*)d_in[10];
    float* out = (float*)d_out;

    hist_kernel<<<(N_EDGES + 511) / 512, 512>>>(ei);
    scanAB_kernel<<<NB_SCAN, 1024>>>();
    bucket_pack_kernel<<<NB_BUCKET + 20, 512>>>(ei, W0, W1, W2);
    gather_kernel<<<(N_NODES * 32 + 255) / 256, 256>>>((const float4*)ea);

    const int smem_bytes = 2 * TILE_M * SW * (int)sizeof(__half) + 2 * TILE_M * (int)sizeof(float);
    cudaFuncSetAttribute(mlp_kernel, cudaFuncAttributeMaxDynamicSharedMemorySize, smem_bytes);
    int grid = (N_NODES + TILE_M - 1) / TILE_M;
    mlp_kernel<<<grid, 256, smem_bytes>>>(x, b0, b1, b2, lg, lb, out);
}